// round 1
// baseline (speedup 1.0000x reference)
#include <cuda_runtime.h>
#include <cuda_bf16.h>
#include <math.h>
#include <stdint.h>

// ---------------- problem constants ----------------
#define L_TOK   131040          // 8*91*180
#define TOKW    138240          // 960 windows * 144 tokens
#define DIMC    192
#define HID     768
#define NHEAD   6
#define HDIM    32
#define NTOK    144             // tokens per window (2*6*12)
#define NWIN    64              // windows per lon-group (4*16)
#define NLON    15
#define BWN     960             // NLON*NWIN

// ---------------- scratch buffers (static device allocations) ----------------
__device__ __nv_bfloat16 g_A1[(size_t)TOKW * DIMC];          // LN1 + windowed, bf16
__device__ __nv_bfloat16 g_qkv[(size_t)TOKW * 3 * DIMC];     // qkv bf16
__device__ float         g_biasPre[(size_t)NHEAD * NWIN * NTOK * NTOK];
__device__ __nv_bfloat16 g_attnout[(size_t)TOKW * DIMC];
__device__ float         g_projout[(size_t)TOKW * DIMC];
__device__ float         g_x1[(size_t)L_TOK * DIMC];
__device__ __nv_bfloat16 g_h2in[(size_t)L_TOK * DIMC];
__device__ __nv_bfloat16 g_h2mid[(size_t)L_TOK * HID];
__device__ __nv_bfloat16 g_wqkv[3 * DIMC * DIMC];
__device__ __nv_bfloat16 g_wproj[DIMC * DIMC];
__device__ __nv_bfloat16 g_wfc1[HID * DIMC];
__device__ __nv_bfloat16 g_wfc2[DIMC * HID];

// ---------------- helpers ----------------
__global__ void f2bf_kernel(const float* __restrict__ s, __nv_bfloat16* __restrict__ d, int n) {
    int i = blockIdx.x * blockDim.x + threadIdx.x;
    if (i < n) d[i] = __float2bfloat16(s[i]);
}

// block (192 threads) mean/var over the 192 channels
__device__ __forceinline__ void blk_stats192(float v, float& mean, float& var) {
    float s = v, s2 = v * v;
    #pragma unroll
    for (int o = 16; o > 0; o >>= 1) {
        s  += __shfl_xor_sync(0xffffffffu, s, o);
        s2 += __shfl_xor_sync(0xffffffffu, s2, o);
    }
    __shared__ float sh1[6], sh2[6], res[2];
    int wp = threadIdx.x >> 5;
    if ((threadIdx.x & 31) == 0) { sh1[wp] = s; sh2[wp] = s2; }
    __syncthreads();
    if (threadIdx.x == 0) {
        float a = 0.f, b2 = 0.f;
        #pragma unroll
        for (int i2 = 0; i2 < 6; i2++) { a += sh1[i2]; b2 += sh2[i2]; }
        float m = a * (1.f / 192.f);
        res[0] = m;
        res[1] = b2 * (1.f / 192.f) - m * m;
    }
    __syncthreads();
    mean = res[0]; var = res[1];
}

// ---------------- LN1 + pad + roll + window partition -> g_A1 (bf16) ----------------
__global__ void ln1_window_kernel(const float* __restrict__ x,
                                  const float* __restrict__ w,
                                  const float* __restrict__ b) {
    int t = blockIdx.x;          // window token [0, TOKW)
    int cI = threadIdx.x;        // channel [0, 192)
    int bw = t / NTOK, n = t - bw * NTOK;
    int li = bw >> 6, wdw = bw & 63;
    int wp_i = n / 72, wa_i = (n / 12) % 6, wo_i = n % 12;
    int pl_p  = (wdw >> 4) * 2 + wp_i;
    int lat_p = (wdw & 15) * 6 + wa_i;
    int lon_p = li * 12 + wo_i;
    // roll(-shift): rolled[p] = padded[(p + shift) mod size]
    int pl_s  = (pl_p + 1) & 7;
    int lat_s = (lat_p + 3) % 96;
    int lon_s = (lon_p + 6) % 180;
    int lat_o = lat_s - 2;
    bool valid = (lat_o >= 0) && (lat_o < 91);
    float v = 0.f;
    if (valid) {
        size_t src = ((size_t)(pl_s * 91 + lat_o) * 180 + lon_s);
        v = x[src * DIMC + cI];
    }
    float mean, var;
    blk_stats192(v, mean, var);
    float h = 0.f;
    if (valid) h = (v - mean) * rsqrtf(var + 1e-5f) * w[cI] + b[cI];
    g_A1[(size_t)t * DIMC + cI] = __float2bfloat16(h);
}

// ---------------- earth position bias precompute: [head][w][i][j] ----------------
__global__ void bias_pre_kernel(const float* __restrict__ btab) {
    int hw = blockIdx.x;                 // [0, 384)
    int head = hw / NWIN, wdw = hw % NWIN;
    int i = threadIdx.x;                 // [0, 144)
    __shared__ int zz[NTOK], hh[NTOK], ww[NTOK];
    int zi = i / 72, hi = (i / 12) % 6, wi = i % 12;
    zz[i] = zi; hh[i] = hi; ww[i] = wi;
    __syncthreads();
    float* dst = g_biasPre + ((size_t)(head * NWIN + wdw) * NTOK + i) * NTOK;
    int base2 = wdw * NHEAD + head;
    for (int j = 0; j < NTOK; j++) {
        int bidx = (zi + 2 * zz[j]) * 828 + (hi + 6 * hh[j]) * 23 + (wi - ww[j] + 11);
        dst[j] = btab[(size_t)bidx * (NWIN * NHEAD) + base2];
    }
}

// ---------------- bf16 GEMM: C[M,N] = A[M,K] @ B[N,K]^T (+ epilogue) ----------------
// MODE 0: fp32 out + bias    MODE 1: bf16 out + bias
// MODE 2: gelu(acc+bias) -> bf16     MODE 3: Out = X1 + acc + bias (fp32)
__device__ __forceinline__ void mma16816(float* d, const uint32_t* a, const uint32_t* b) {
    asm volatile(
        "mma.sync.aligned.m16n8k16.row.col.f32.bf16.bf16.f32 "
        "{%0,%1,%2,%3}, {%4,%5,%6,%7}, {%8,%9}, {%0,%1,%2,%3};\n"
        : "+f"(d[0]), "+f"(d[1]), "+f"(d[2]), "+f"(d[3])
        : "r"(a[0]), "r"(a[1]), "r"(a[2]), "r"(a[3]), "r"(b[0]), "r"(b[1]));
}

template <int MODE>
__global__ __launch_bounds__(256) void gemm_bf16(
    int M, int N, int K,
    const __nv_bfloat16* __restrict__ A,
    const __nv_bfloat16* __restrict__ Bw,
    const float* __restrict__ bias,
    float* __restrict__ Cf,
    __nv_bfloat16* __restrict__ Cb,
    const float* __restrict__ X1,
    float* __restrict__ Out) {
    __shared__ __align__(16) __nv_bfloat16 As[2][128][40];
    __shared__ __align__(16) __nv_bfloat16 Bs[2][64][40];

    const int tid = threadIdx.x;
    const int m0 = blockIdx.y * 128;
    const int n0 = blockIdx.x * 64;
    const int warp = tid >> 5, lane = tid & 31;
    const int wm = (warp >> 1) * 32, wn = (warp & 1) * 32;
    const int g = lane >> 2, c4 = lane & 3;
    const int lr = tid >> 2;            // 0..63
    const int lc = (tid & 3) * 8;       // 0,8,16,24

    float acc[2][4][4];
    #pragma unroll
    for (int a2 = 0; a2 < 2; a2++)
        #pragma unroll
        for (int b2 = 0; b2 < 4; b2++)
            #pragma unroll
            for (int c2 = 0; c2 < 4; c2++) acc[a2][b2][c2] = 0.f;

    const uint4 z4 = make_uint4(0u, 0u, 0u, 0u);
    const int KT = K >> 5;

    {   // prologue: stage 0
        int r0 = m0 + lr, r1 = m0 + 64 + lr;
        uint4 a0 = (r0 < M) ? *(const uint4*)(A + (size_t)r0 * K + lc) : z4;
        uint4 a1 = (r1 < M) ? *(const uint4*)(A + (size_t)r1 * K + lc) : z4;
        uint4 b0 = *(const uint4*)(Bw + (size_t)(n0 + lr) * K + lc);
        *(uint4*)&As[0][lr][lc] = a0;
        *(uint4*)&As[0][64 + lr][lc] = a1;
        *(uint4*)&Bs[0][lr][lc] = b0;
    }
    __syncthreads();

    for (int kt = 0; kt < KT; kt++) {
        const int s = kt & 1;
        uint4 na0 = z4, na1 = z4, nb0 = z4;
        const bool more = (kt + 1 < KT);
        if (more) {
            int k0 = (kt + 1) << 5;
            int r0 = m0 + lr, r1 = m0 + 64 + lr;
            na0 = (r0 < M) ? *(const uint4*)(A + (size_t)r0 * K + k0 + lc) : z4;
            na1 = (r1 < M) ? *(const uint4*)(A + (size_t)r1 * K + k0 + lc) : z4;
            nb0 = *(const uint4*)(Bw + (size_t)(n0 + lr) * K + k0 + lc);
        }
        #pragma unroll
        for (int kk = 0; kk < 32; kk += 16) {
            uint32_t af[2][4], bfr[4][2];
            #pragma unroll
            for (int mi = 0; mi < 2; mi++) {
                const __nv_bfloat16* ap = &As[s][wm + mi * 16 + g][kk + 2 * c4];
                af[mi][0] = *(const uint32_t*)ap;
                af[mi][1] = *(const uint32_t*)(ap + 8 * 40);
                af[mi][2] = *(const uint32_t*)(ap + 8);
                af[mi][3] = *(const uint32_t*)(ap + 8 * 40 + 8);
            }
            #pragma unroll
            for (int ni = 0; ni < 4; ni++) {
                const __nv_bfloat16* bp = &Bs[s][wn + ni * 8 + g][kk + 2 * c4];
                bfr[ni][0] = *(const uint32_t*)bp;
                bfr[ni][1] = *(const uint32_t*)(bp + 8);
            }
            #pragma unroll
            for (int mi = 0; mi < 2; mi++)
                #pragma unroll
                for (int ni = 0; ni < 4; ni++)
                    mma16816(acc[mi][ni], af[mi], bfr[ni]);
        }
        if (more) {
            const int s1 = s ^ 1;
            *(uint4*)&As[s1][lr][lc] = na0;
            *(uint4*)&As[s1][64 + lr][lc] = na1;
            *(uint4*)&Bs[s1][lr][lc] = nb0;
        }
        __syncthreads();
    }

    // epilogue
    #pragma unroll
    for (int mi = 0; mi < 2; mi++) {
        #pragma unroll
        for (int ni = 0; ni < 4; ni++) {
            int row0 = m0 + wm + mi * 16 + g;
            int row1 = row0 + 8;
            int col0 = n0 + wn + ni * 8 + 2 * c4;
            float b0v = bias[col0], b1v = bias[col0 + 1];
            float vv[4] = { acc[mi][ni][0] + b0v, acc[mi][ni][1] + b1v,
                            acc[mi][ni][2] + b0v, acc[mi][ni][3] + b1v };
            int rows[2] = { row0, row1 };
            #pragma unroll
            for (int rr = 0; rr < 2; rr++) {
                if (rows[rr] >= M) continue;
                #pragma unroll
                for (int cc = 0; cc < 2; cc++) {
                    size_t off = (size_t)rows[rr] * N + col0 + cc;
                    float v = vv[rr * 2 + cc];
                    if (MODE == 0) {
                        Cf[off] = v;
                    } else if (MODE == 1) {
                        Cb[off] = __float2bfloat16(v);
                    } else if (MODE == 2) {
                        float gl = 0.5f * v * (1.0f + erff(v * 0.70710678118654752f));
                        Cb[off] = __float2bfloat16(gl);
                    } else {
                        Out[off] = X1[off] + v;
                    }
                }
            }
        }
    }
}

// ---------------- fused windowed attention (one block = one (window, head)) ----------------
#define ATTN_SMEM ((3 * NTOK * 34 + NTOK * NTOK) * 2 + NTOK * 4)

__global__ __launch_bounds__(256) void attn_kernel() {
    const int head = blockIdx.x;
    const int bw = blockIdx.y;
    const int li = bw / NWIN;
    const int wdw = bw - li * NWIN;
    const int tid = threadIdx.x;
    const int lane = tid & 31;
    const int warp = tid >> 5;

    extern __shared__ unsigned char smraw[];
    __nv_bfloat16* sq = (__nv_bfloat16*)smraw;
    __nv_bfloat16* sk = sq + NTOK * 34;
    __nv_bfloat16* sv = sk + NTOK * 34;
    __nv_bfloat16* sP = sv + NTOK * 34;
    int* sreg = (int*)(sP + NTOK * NTOK);

    const float qscale = 0.17677669529663687f;   // 1/sqrt(32)
    for (int idx = tid; idx < NTOK * HDIM; idx += 256) {
        int j = idx >> 5, d = idx & 31;
        size_t base = (size_t)(bw * NTOK + j) * (3 * DIMC) + head * HDIM + d;
        sq[j * 34 + d] = __float2bfloat16(__bfloat162float(g_qkv[base]) * qscale);
        sk[j * 34 + d] = g_qkv[base + DIMC];
        sv[j * 34 + d] = g_qkv[base + 2 * DIMC];
    }
    if (tid < NTOK) {
        int n = tid;
        int wp_i = n / 72, wa_i = (n / 12) % 6, wo_i = n % 12;
        int pl_p  = (wdw >> 4) * 2 + wp_i;
        int lat_p = (wdw & 15) * 6 + wa_i;
        int lon_p = li * 12 + wo_i;
        int rpl  = pl_p  < 6  ? 0 : (pl_p  < 7  ? 1 : 2);
        int rlat = lat_p < 90 ? 0 : (lat_p < 93 ? 1 : 2);
        int rlon = lon_p < 174 ? 0 : 1;
        sreg[tid] = (rpl * 3 + rlat) * 3 + rlon;
    }
    __syncthreads();

    const float* brow0 = g_biasPre + (size_t)(head * NWIN + wdw) * NTOK * NTOK;
    for (int i = warp; i < NTOK; i += 8) {
        float qr[HDIM];
        #pragma unroll
        for (int d = 0; d < HDIM; d++) qr[d] = __bfloat162float(sq[i * 34 + d]);
        const int ri = sreg[i];
        const float* brow = brow0 + (size_t)i * NTOK;
        float vals[5];
        float mx = -1e30f;
        #pragma unroll
        for (int jj = 0; jj < 5; jj++) {
            int j = lane + jj * 32;
            float s = -1e30f;
            if (j < NTOK) {
                float a = 0.f;
                #pragma unroll
                for (int d = 0; d < HDIM; d++) a += qr[d] * __bfloat162float(sk[j * 34 + d]);
                s = a + brow[j];
                if (sreg[j] != ri) s -= 100.f;
            }
            vals[jj] = s;
            mx = fmaxf(mx, s);
        }
        #pragma unroll
        for (int o = 16; o > 0; o >>= 1) mx = fmaxf(mx, __shfl_xor_sync(0xffffffffu, mx, o));
        float sum = 0.f;
        #pragma unroll
        for (int jj = 0; jj < 5; jj++) {
            int j = lane + jj * 32;
            float e = 0.f;
            if (j < NTOK) e = __expf(vals[jj] - mx);
            vals[jj] = e; sum += e;
        }
        #pragma unroll
        for (int o = 16; o > 0; o >>= 1) sum += __shfl_xor_sync(0xffffffffu, sum, o);
        float inv = 1.f / sum;
        #pragma unroll
        for (int jj = 0; jj < 5; jj++) {
            int j = lane + jj * 32;
            if (j < NTOK) sP[i * NTOK + j] = __float2bfloat16(vals[jj] * inv);
        }
    }
    __syncthreads();

    for (int i = warp; i < NTOK; i += 8) {
        float a = 0.f;
        #pragma unroll 4
        for (int j = 0; j < NTOK; j++)
            a += __bfloat162float(sP[i * NTOK + j]) * __bfloat162float(sv[j * 34 + lane]);
        g_attnout[(size_t)(bw * NTOK + i) * DIMC + head * HDIM + lane] = __float2bfloat16(a);
    }
}

// ---------------- un-window + residual + LN2 ----------------
__global__ void unwin_res_ln2_kernel(const float* __restrict__ x,
                                     const float* __restrict__ w,
                                     const float* __restrict__ b) {
    int t = blockIdx.x;          // [0, L_TOK)
    int cI = threadIdx.x;
    int pl = t / (91 * 180);
    int rem = t - pl * (91 * 180);
    int lat = rem / 180, lon = rem % 180;
    int pl_p  = (pl + 7) & 7;            // (pl - 1) mod 8
    int lat_p = (lat + 95) % 96;         // (lat + 2 - 3) mod 96
    int lon_p = (lon + 174) % 180;       // (lon - 6) mod 180
    int plg = pl_p >> 1, wp_i = pl_p & 1;
    int latg = lat_p / 6, wa_i = lat_p % 6;
    int li = lon_p / 12, wo_i = lon_p % 12;
    int wdw = plg * 16 + latg;
    int n = (wp_i * 6 + wa_i) * 12 + wo_i;
    size_t slot = ((size_t)((li * NWIN + wdw) * NTOK + n)) * DIMC + cI;
    float v = x[(size_t)t * DIMC + cI] + g_projout[slot];
    g_x1[(size_t)t * DIMC + cI] = v;
    float mean, var;
    blk_stats192(v, mean, var);
    float h = (v - mean) * rsqrtf(var + 1e-5f) * w[cI] + b[cI];
    g_h2in[(size_t)t * DIMC + cI] = __float2bfloat16(h);
}

// ---------------- launch ----------------
extern "C" void kernel_launch(void* const* d_in, const int* in_sizes, int n_in,
                              void* d_out, int out_size) {
    const float* x     = (const float*)d_in[0];
    const float* n1w   = (const float*)d_in[1];
    const float* n1b   = (const float*)d_in[2];
    const float* qkvw  = (const float*)d_in[3];
    const float* qkvb  = (const float*)d_in[4];
    const float* btab  = (const float*)d_in[5];
    const float* projw = (const float*)d_in[6];
    const float* projb = (const float*)d_in[7];
    const float* n2w   = (const float*)d_in[8];
    const float* n2b   = (const float*)d_in[9];
    const float* fc1w  = (const float*)d_in[10];
    const float* fc1b  = (const float*)d_in[11];
    const float* fc2w  = (const float*)d_in[12];
    const float* fc2b  = (const float*)d_in[13];
    float* out = (float*)d_out;

    void *pA1, *pqkv, *pattn, *pproj, *px1, *ph2in, *ph2mid;
    void *pwqkv, *pwproj, *pwfc1, *pwfc2;
    cudaGetSymbolAddress(&pA1, g_A1);
    cudaGetSymbolAddress(&pqkv, g_qkv);
    cudaGetSymbolAddress(&pattn, g_attnout);
    cudaGetSymbolAddress(&pproj, g_projout);
    cudaGetSymbolAddress(&px1, g_x1);
    cudaGetSymbolAddress(&ph2in, g_h2in);
    cudaGetSymbolAddress(&ph2mid, g_h2mid);
    cudaGetSymbolAddress(&pwqkv, g_wqkv);
    cudaGetSymbolAddress(&pwproj, g_wproj);
    cudaGetSymbolAddress(&pwfc1, g_wfc1);
    cudaGetSymbolAddress(&pwfc2, g_wfc2);

    cudaFuncSetAttribute(attn_kernel, cudaFuncAttributeMaxDynamicSharedMemorySize, 72 * 1024);

    // weight conversions (bf16)
    f2bf_kernel<<<(3 * DIMC * DIMC + 255) / 256, 256>>>(qkvw, (__nv_bfloat16*)pwqkv, 3 * DIMC * DIMC);
    f2bf_kernel<<<(DIMC * DIMC + 255) / 256, 256>>>(projw, (__nv_bfloat16*)pwproj, DIMC * DIMC);
    f2bf_kernel<<<(HID * DIMC + 255) / 256, 256>>>(fc1w, (__nv_bfloat16*)pwfc1, HID * DIMC);
    f2bf_kernel<<<(DIMC * HID + 255) / 256, 256>>>(fc2w, (__nv_bfloat16*)pwfc2, DIMC * HID);

    // LN1 + window partition, bias table precompute
    ln1_window_kernel<<<TOKW, DIMC>>>(x, n1w, n1b);
    bias_pre_kernel<<<NHEAD * NWIN, NTOK>>>(btab);

    // QKV GEMM -> bf16
    gemm_bf16<1><<<dim3(9, TOKW / 128), 256>>>(TOKW, 3 * DIMC, DIMC,
        (const __nv_bfloat16*)pA1, (const __nv_bfloat16*)pwqkv, qkvb,
        nullptr, (__nv_bfloat16*)pqkv, nullptr, nullptr);

    // fused windowed attention
    attn_kernel<<<dim3(NHEAD, BWN), 256, ATTN_SMEM>>>();

    // proj GEMM -> fp32 (window layout)
    gemm_bf16<0><<<dim3(3, TOKW / 128), 256>>>(TOKW, DIMC, DIMC,
        (const __nv_bfloat16*)pattn, (const __nv_bfloat16*)pwproj, projb,
        (float*)pproj, nullptr, nullptr, nullptr);

    // un-window + residual + LN2
    unwin_res_ln2_kernel<<<L_TOK, DIMC>>>(x, n2w, n2b);

    // fc1 (+ exact GELU) -> bf16
    gemm_bf16<2><<<dim3(12, (L_TOK + 127) / 128), 256>>>(L_TOK, HID, DIMC,
        (const __nv_bfloat16*)ph2in, (const __nv_bfloat16*)pwfc1, fc1b,
        nullptr, (__nv_bfloat16*)ph2mid, nullptr, nullptr);

    // fc2 + residual -> d_out
    gemm_bf16<3><<<dim3(3, (L_TOK + 127) / 128), 256>>>(L_TOK, DIMC, HID,
        (const __nv_bfloat16*)ph2mid, (const __nv_bfloat16*)pwfc2, fc2b,
        nullptr, nullptr, (const float*)px1, out);
}

// round 2
// speedup vs baseline: 1.2661x; 1.2661x over previous
#include <cuda_runtime.h>
#include <cuda_bf16.h>
#include <math.h>
#include <stdint.h>

// ---------------- problem constants ----------------
#define L_TOK   131040          // 8*91*180
#define TOKW    138240          // 960 windows * 144 tokens
#define DIMC    192
#define HID     768
#define NHEAD   6
#define HDIM    32
#define NTOK    144             // tokens per window (2*6*12)
#define NWIN    64              // windows per lon-group (4*16)
#define NLON    15
#define BWN     960             // NLON*NWIN

// GEMM tiling
#define BM 128
#define BN 192
#define BK 32
#define GSTAGES 3
#define PADK 40
#define STAGE_ELEMS ((BM + BN) * PADK)   // 12800 elems, 25600 B
#define GEMM_SMEM (STAGE_ELEMS * 2 * GSTAGES)  // 76800 B

// ---------------- scratch buffers ----------------
__device__ __nv_bfloat16 g_A1[(size_t)TOKW * DIMC];
__device__ __nv_bfloat16 g_qkv[(size_t)TOKW * 3 * DIMC];
__device__ float         g_biasPre[(size_t)NHEAD * NWIN * NTOK * NTOK];
__device__ __nv_bfloat16 g_attnout[(size_t)TOKW * DIMC];
__device__ float         g_projout[(size_t)TOKW * DIMC];
__device__ float         g_x1[(size_t)L_TOK * DIMC];
__device__ __nv_bfloat16 g_h2in[(size_t)L_TOK * DIMC];
__device__ __nv_bfloat16 g_h2mid[(size_t)L_TOK * HID];
__device__ __nv_bfloat16 g_wqkv[3 * DIMC * DIMC];
__device__ __nv_bfloat16 g_wproj[DIMC * DIMC];
__device__ __nv_bfloat16 g_wfc1[HID * DIMC];
__device__ __nv_bfloat16 g_wfc2[DIMC * HID];

// ---------------- helpers ----------------
__global__ void f2bf_kernel(const float* __restrict__ s, __nv_bfloat16* __restrict__ d, int n) {
    int i = blockIdx.x * blockDim.x + threadIdx.x;
    if (i < n) d[i] = __float2bfloat16(s[i]);
}

__device__ __forceinline__ void cp_async16(uint32_t saddr, const void* gptr, bool pred) {
    int sz = pred ? 16 : 0;
    asm volatile("cp.async.cg.shared.global [%0], [%1], 16, %2;\n"
                 :: "r"(saddr), "l"(gptr), "r"(sz));
}

__device__ __forceinline__ void ldsm4(uint32_t* r, uint32_t addr) {
    asm volatile("ldmatrix.sync.aligned.m8n8.x4.shared.b16 {%0,%1,%2,%3}, [%4];\n"
                 : "=r"(r[0]), "=r"(r[1]), "=r"(r[2]), "=r"(r[3]) : "r"(addr));
}

__device__ __forceinline__ void mma16816(float* d, const uint32_t* a, const uint32_t* b) {
    asm volatile(
        "mma.sync.aligned.m16n8k16.row.col.f32.bf16.bf16.f32 "
        "{%0,%1,%2,%3}, {%4,%5,%6,%7}, {%8,%9}, {%0,%1,%2,%3};\n"
        : "+f"(d[0]), "+f"(d[1]), "+f"(d[2]), "+f"(d[3])
        : "r"(a[0]), "r"(a[1]), "r"(a[2]), "r"(a[3]), "r"(b[0]), "r"(b[1]));
}

// ---------------- LN1 + pad + roll + window partition (warp per token) ----------------
__global__ __launch_bounds__(256) void ln1_window_kernel(const float* __restrict__ x,
                                                          const float* __restrict__ w,
                                                          const float* __restrict__ b) {
    int t = blockIdx.x * 8 + (threadIdx.x >> 5);   // window token [0, TOKW)
    int lane = threadIdx.x & 31;
    int bw = t / NTOK, n = t - bw * NTOK;
    int li = bw >> 6, wdw = bw & 63;
    int wp_i = n / 72, wa_i = (n / 12) % 6, wo_i = n % 12;
    int pl_p  = (wdw >> 4) * 2 + wp_i;
    int lat_p = (wdw & 15) * 6 + wa_i;
    int lon_p = li * 12 + wo_i;
    int pl_s  = (pl_p + 1) & 7;
    int lat_s = (lat_p + 3) % 96;
    int lon_s = (lon_p + 6) % 180;
    int lat_o = lat_s - 2;
    bool valid = (lat_o >= 0) && (lat_o < 91);
    size_t src = valid ? ((size_t)(pl_s * 91 + lat_o) * 180 + lon_s) * DIMC : 0;
    float v[6]; float s = 0.f, s2 = 0.f;
    #pragma unroll
    for (int k = 0; k < 6; k++) {
        float vv = valid ? x[src + lane + 32 * k] : 0.f;
        v[k] = vv; s += vv; s2 += vv * vv;
    }
    #pragma unroll
    for (int o = 16; o > 0; o >>= 1) {
        s  += __shfl_xor_sync(0xffffffffu, s, o);
        s2 += __shfl_xor_sync(0xffffffffu, s2, o);
    }
    float mean = s * (1.f / 192.f);
    float var  = s2 * (1.f / 192.f) - mean * mean;
    float rstd = rsqrtf(var + 1e-5f);
    #pragma unroll
    for (int k = 0; k < 6; k++) {
        int c = lane + 32 * k;
        float h = valid ? (v[k] - mean) * rstd * w[c] + b[c] : 0.f;
        g_A1[(size_t)t * DIMC + c] = __float2bfloat16(h);
    }
}

// ---------------- earth position bias precompute: [head][w][i][j] ----------------
__global__ __launch_bounds__(256) void bias_pre_kernel(const float* __restrict__ btab) {
    int hw = blockIdx.x;                 // head*NWIN + wdw
    int head = hw / NWIN, wdw = hw % NWIN;
    int base2 = wdw * NHEAD + head;
    float* dst = g_biasPre + (size_t)hw * NTOK * NTOK;
    for (int e = threadIdx.x; e < NTOK * NTOK; e += 256) {
        int i = e / NTOK, j = e - i * NTOK;
        int zi = i / 72, hi = (i / 12) % 6, wi = i % 12;
        int zj = j / 72, hj = (j / 12) % 6, wj = j % 12;
        int bidx = (zi + 2 * zj) * 828 + (hi + 6 * hj) * 23 + (wi - wj + 11);
        dst[e] = btab[(size_t)bidx * (NWIN * NHEAD) + base2];
    }
}

// ---------------- bf16 GEMM v2: cp.async + ldmatrix, 128x192 tile ----------------
// MODE 0: fp32 out + bias    MODE 1: bf16 out + bias
// MODE 2: gelu(acc+bias) -> bf16     MODE 3: Out = X1 + acc + bias (fp32)
template <int MODE>
__global__ __launch_bounds__(256, 1) void gemm2(
    int M, int N, int K,
    const __nv_bfloat16* __restrict__ A,
    const __nv_bfloat16* __restrict__ Bw,
    const float* __restrict__ bias,
    float* __restrict__ Cf,
    __nv_bfloat16* __restrict__ Cb,
    const float* __restrict__ X1,
    float* __restrict__ Out) {
    extern __shared__ __align__(16) unsigned char smraw[];
    uint32_t smem_u32 = (uint32_t)__cvta_generic_to_shared(smraw);

    const int tid = threadIdx.x;
    const int lane = tid & 31, warp = tid >> 5;
    const int m0 = blockIdx.y * BM;
    const int n0 = blockIdx.x * BN;
    const int wm = (warp >> 2) * 64;
    const int wn = (warp & 3) * 48;
    const int KT = K >> 5;

    float acc[4][6][4];
    #pragma unroll
    for (int a = 0; a < 4; a++)
        #pragma unroll
        for (int b2 = 0; b2 < 6; b2++)
            #pragma unroll
            for (int c = 0; c < 4; c++) acc[a][b2][c] = 0.f;

    auto load_stage = [&](int stage, int kt) {
        const int kb = kt << 5;
        uint32_t sbase = smem_u32 + stage * (STAGE_ELEMS * 2);
        #pragma unroll
        for (int i = 0; i < 2; i++) {
            int c = tid + i * 256;
            int row = c >> 2, col = (c & 3) << 3;
            int gr = m0 + row;
            bool p = gr < M;
            const __nv_bfloat16* gp = A + (size_t)(p ? gr : 0) * K + kb + col;
            cp_async16(sbase + (uint32_t)(row * PADK + col) * 2, gp, p);
        }
        uint32_t bbase = sbase + BM * PADK * 2;
        #pragma unroll
        for (int i = 0; i < 3; i++) {
            int c = tid + i * 256;
            int row = c >> 2, col = (c & 3) << 3;
            const __nv_bfloat16* gp = Bw + (size_t)(n0 + row) * K + kb + col;
            cp_async16(bbase + (uint32_t)(row * PADK + col) * 2, gp, true);
        }
    };

    #pragma unroll
    for (int s = 0; s < GSTAGES - 1; s++) {
        load_stage(s, s);
        asm volatile("cp.async.commit_group;\n");
    }

    for (int kt = 0; kt < KT; kt++) {
        asm volatile("cp.async.wait_group 1;\n");
        __syncthreads();
        uint32_t sbase = smem_u32 + (kt % GSTAGES) * (STAGE_ELEMS * 2);
        #pragma unroll
        for (int kk = 0; kk < 32; kk += 16) {
            uint32_t af[4][4], bfr[3][4];
            #pragma unroll
            for (int mi = 0; mi < 4; mi++) {
                uint32_t addr = sbase +
                    (uint32_t)(((wm + mi * 16 + (lane & 15)) * PADK) + kk + ((lane & 16) >> 1)) * 2;
                ldsm4(af[mi], addr);
            }
            #pragma unroll
            for (int nb = 0; nb < 3; nb++) {
                int nr = wn + nb * 16 + (lane & 7) + ((lane & 16) >> 1);
                uint32_t addr = sbase + BM * PADK * 2 +
                    (uint32_t)(nr * PADK + kk + (lane & 8)) * 2;
                ldsm4(bfr[nb], addr);
            }
            #pragma unroll
            for (int mi = 0; mi < 4; mi++)
                #pragma unroll
                for (int ni = 0; ni < 6; ni++)
                    mma16816(acc[mi][ni], af[mi], &bfr[ni >> 1][(ni & 1) * 2]);
        }
        int kn = kt + GSTAGES - 1;
        if (kn < KT) load_stage(kn % GSTAGES, kn);
        asm volatile("cp.async.commit_group;\n");
    }

    // epilogue
    const int g = lane >> 2, c4 = lane & 3;
    #pragma unroll
    for (int mi = 0; mi < 4; mi++) {
        #pragma unroll
        for (int ni = 0; ni < 6; ni++) {
            int row0 = m0 + wm + mi * 16 + g;
            int col0 = n0 + wn + ni * 8 + 2 * c4;
            float2 bv = *(const float2*)(bias + col0);
            #pragma unroll
            for (int rr = 0; rr < 2; rr++) {
                int row = row0 + rr * 8;
                if (row >= M) continue;
                float v0 = acc[mi][ni][rr * 2 + 0] + bv.x;
                float v1 = acc[mi][ni][rr * 2 + 1] + bv.y;
                size_t off = (size_t)row * N + col0;
                if (MODE == 0) {
                    *(float2*)(Cf + off) = make_float2(v0, v1);
                } else if (MODE == 1) {
                    *(__nv_bfloat162*)(Cb + off) =
                        __nv_bfloat162(__float2bfloat16(v0), __float2bfloat16(v1));
                } else if (MODE == 2) {
                    float g0 = 0.5f * v0 * (1.0f + erff(v0 * 0.70710678118654752f));
                    float g1 = 0.5f * v1 * (1.0f + erff(v1 * 0.70710678118654752f));
                    *(__nv_bfloat162*)(Cb + off) =
                        __nv_bfloat162(__float2bfloat16(g0), __float2bfloat16(g1));
                } else {
                    float2 xv = *(const float2*)(X1 + off);
                    *(float2*)(Out + off) = make_float2(xv.x + v0, xv.y + v1);
                }
            }
        }
    }
}

// ---------------- fused windowed attention (one block = one (window, head)) ----------------
#define ATTN_SMEM ((3 * NTOK * 34 + NTOK * NTOK) * 2 + NTOK * 4)

__global__ __launch_bounds__(256) void attn_kernel() {
    const int head = blockIdx.x;
    const int bw = blockIdx.y;
    const int li = bw / NWIN;
    const int wdw = bw - li * NWIN;
    const int tid = threadIdx.x;
    const int lane = tid & 31;
    const int warp = tid >> 5;

    extern __shared__ unsigned char smraw[];
    __nv_bfloat16* sq = (__nv_bfloat16*)smraw;
    __nv_bfloat16* sk = sq + NTOK * 34;
    __nv_bfloat16* sv = sk + NTOK * 34;
    __nv_bfloat16* sP = sv + NTOK * 34;
    int* sreg = (int*)(sP + NTOK * NTOK);

    const float qscale = 0.17677669529663687f;   // 1/sqrt(32)
    for (int idx = tid; idx < NTOK * HDIM; idx += 256) {
        int j = idx >> 5, d = idx & 31;
        size_t base = (size_t)(bw * NTOK + j) * (3 * DIMC) + head * HDIM + d;
        sq[j * 34 + d] = __float2bfloat16(__bfloat162float(g_qkv[base]) * qscale);
        sk[j * 34 + d] = g_qkv[base + DIMC];
        sv[j * 34 + d] = g_qkv[base + 2 * DIMC];
    }
    if (tid < NTOK) {
        int n = tid;
        int wp_i = n / 72, wa_i = (n / 12) % 6, wo_i = n % 12;
        int pl_p  = (wdw >> 4) * 2 + wp_i;
        int lat_p = (wdw & 15) * 6 + wa_i;
        int lon_p = li * 12 + wo_i;
        int rpl  = pl_p  < 6  ? 0 : (pl_p  < 7  ? 1 : 2);
        int rlat = lat_p < 90 ? 0 : (lat_p < 93 ? 1 : 2);
        int rlon = lon_p < 174 ? 0 : 1;
        sreg[tid] = (rpl * 3 + rlat) * 3 + rlon;
    }
    __syncthreads();

    const float* brow0 = g_biasPre + (size_t)(head * NWIN + wdw) * NTOK * NTOK;
    for (int i = warp; i < NTOK; i += 8) {
        float qr[HDIM];
        #pragma unroll
        for (int d = 0; d < HDIM; d++) qr[d] = __bfloat162float(sq[i * 34 + d]);
        const int ri = sreg[i];
        const float* brow = brow0 + (size_t)i * NTOK;
        float vals[5];
        float mx = -1e30f;
        #pragma unroll
        for (int jj = 0; jj < 5; jj++) {
            int j = lane + jj * 32;
            float s = -1e30f;
            if (j < NTOK) {
                float a = 0.f;
                #pragma unroll
                for (int d = 0; d < HDIM; d++) a += qr[d] * __bfloat162float(sk[j * 34 + d]);
                s = a + brow[j];
                if (sreg[j] != ri) s -= 100.f;
            }
            vals[jj] = s;
            mx = fmaxf(mx, s);
        }
        #pragma unroll
        for (int o = 16; o > 0; o >>= 1) mx = fmaxf(mx, __shfl_xor_sync(0xffffffffu, mx, o));
        float sum = 0.f;
        #pragma unroll
        for (int jj = 0; jj < 5; jj++) {
            int j = lane + jj * 32;
            float e = 0.f;
            if (j < NTOK) e = __expf(vals[jj] - mx);
            vals[jj] = e; sum += e;
        }
        #pragma unroll
        for (int o = 16; o > 0; o >>= 1) sum += __shfl_xor_sync(0xffffffffu, sum, o);
        float inv = 1.f / sum;
        #pragma unroll
        for (int jj = 0; jj < 5; jj++) {
            int j = lane + jj * 32;
            if (j < NTOK) sP[i * NTOK + j] = __float2bfloat16(vals[jj] * inv);
        }
    }
    __syncthreads();

    for (int i = warp; i < NTOK; i += 8) {
        float a = 0.f;
        #pragma unroll 4
        for (int j = 0; j < NTOK; j++)
            a += __bfloat162float(sP[i * NTOK + j]) * __bfloat162float(sv[j * 34 + lane]);
        g_attnout[(size_t)(bw * NTOK + i) * DIMC + head * HDIM + lane] = __float2bfloat16(a);
    }
}

// ---------------- un-window + residual + LN2 (warp per token) ----------------
__global__ __launch_bounds__(256) void unwin_res_ln2_kernel(const float* __restrict__ x,
                                                             const float* __restrict__ w,
                                                             const float* __restrict__ b) {
    int t = blockIdx.x * 8 + (threadIdx.x >> 5);   // [0, L_TOK)
    int lane = threadIdx.x & 31;
    int pl = t / (91 * 180);
    int rem = t - pl * (91 * 180);
    int lat = rem / 180, lon = rem % 180;
    int pl_p  = (pl + 7) & 7;
    int lat_p = (lat + 95) % 96;
    int lon_p = (lon + 174) % 180;
    int plg = pl_p >> 1, wp_i = pl_p & 1;
    int latg = lat_p / 6, wa_i = lat_p % 6;
    int li = lon_p / 12, wo_i = lon_p % 12;
    int wdw = plg * 16 + latg;
    int n = (wp_i * 6 + wa_i) * 12 + wo_i;
    size_t slot = ((size_t)((li * NWIN + wdw) * NTOK + n)) * DIMC;
    size_t base = (size_t)t * DIMC;
    float v[6]; float s = 0.f, s2 = 0.f;
    #pragma unroll
    for (int k = 0; k < 6; k++) {
        int c = lane + 32 * k;
        float vv = x[base + c] + g_projout[slot + c];
        v[k] = vv; s += vv; s2 += vv * vv;
        g_x1[base + c] = vv;
    }
    #pragma unroll
    for (int o = 16; o > 0; o >>= 1) {
        s  += __shfl_xor_sync(0xffffffffu, s, o);
        s2 += __shfl_xor_sync(0xffffffffu, s2, o);
    }
    float mean = s * (1.f / 192.f);
    float var  = s2 * (1.f / 192.f) - mean * mean;
    float rstd = rsqrtf(var + 1e-5f);
    #pragma unroll
    for (int k = 0; k < 6; k++) {
        int c = lane + 32 * k;
        float h = (v[k] - mean) * rstd * w[c] + b[c];
        g_h2in[base + c] = __float2bfloat16(h);
    }
}

// ---------------- launch ----------------
extern "C" void kernel_launch(void* const* d_in, const int* in_sizes, int n_in,
                              void* d_out, int out_size) {
    const float* x     = (const float*)d_in[0];
    const float* n1w   = (const float*)d_in[1];
    const float* n1b   = (const float*)d_in[2];
    const float* qkvw  = (const float*)d_in[3];
    const float* qkvb  = (const float*)d_in[4];
    const float* btab  = (const float*)d_in[5];
    const float* projw = (const float*)d_in[6];
    const float* projb = (const float*)d_in[7];
    const float* n2w   = (const float*)d_in[8];
    const float* n2b   = (const float*)d_in[9];
    const float* fc1w  = (const float*)d_in[10];
    const float* fc1b  = (const float*)d_in[11];
    const float* fc2w  = (const float*)d_in[12];
    const float* fc2b  = (const float*)d_in[13];
    float* out = (float*)d_out;

    void *pA1, *pqkv, *pattn, *pproj, *px1, *ph2in, *ph2mid;
    void *pwqkv, *pwproj, *pwfc1, *pwfc2;
    cudaGetSymbolAddress(&pA1, g_A1);
    cudaGetSymbolAddress(&pqkv, g_qkv);
    cudaGetSymbolAddress(&pattn, g_attnout);
    cudaGetSymbolAddress(&pproj, g_projout);
    cudaGetSymbolAddress(&px1, g_x1);
    cudaGetSymbolAddress(&ph2in, g_h2in);
    cudaGetSymbolAddress(&ph2mid, g_h2mid);
    cudaGetSymbolAddress(&pwqkv, g_wqkv);
    cudaGetSymbolAddress(&pwproj, g_wproj);
    cudaGetSymbolAddress(&pwfc1, g_wfc1);
    cudaGetSymbolAddress(&pwfc2, g_wfc2);

    cudaFuncSetAttribute(attn_kernel, cudaFuncAttributeMaxDynamicSharedMemorySize, 72 * 1024);
    cudaFuncSetAttribute(gemm2<0>, cudaFuncAttributeMaxDynamicSharedMemorySize, GEMM_SMEM);
    cudaFuncSetAttribute(gemm2<1>, cudaFuncAttributeMaxDynamicSharedMemorySize, GEMM_SMEM);
    cudaFuncSetAttribute(gemm2<2>, cudaFuncAttributeMaxDynamicSharedMemorySize, GEMM_SMEM);
    cudaFuncSetAttribute(gemm2<3>, cudaFuncAttributeMaxDynamicSharedMemorySize, GEMM_SMEM);

    // weight conversions (bf16)
    f2bf_kernel<<<(3 * DIMC * DIMC + 255) / 256, 256>>>(qkvw, (__nv_bfloat16*)pwqkv, 3 * DIMC * DIMC);
    f2bf_kernel<<<(DIMC * DIMC + 255) / 256, 256>>>(projw, (__nv_bfloat16*)pwproj, DIMC * DIMC);
    f2bf_kernel<<<(HID * DIMC + 255) / 256, 256>>>(fc1w, (__nv_bfloat16*)pwfc1, HID * DIMC);
    f2bf_kernel<<<(DIMC * HID + 255) / 256, 256>>>(fc2w, (__nv_bfloat16*)pwfc2, DIMC * HID);

    // LN1 + window partition, bias table precompute
    ln1_window_kernel<<<TOKW / 8, 256>>>(x, n1w, n1b);
    bias_pre_kernel<<<NHEAD * NWIN, 256>>>(btab);

    // QKV GEMM -> bf16
    gemm2<1><<<dim3(3, TOKW / BM), 256, GEMM_SMEM>>>(TOKW, 3 * DIMC, DIMC,
        (const __nv_bfloat16*)pA1, (const __nv_bfloat16*)pwqkv, qkvb,
        nullptr, (__nv_bfloat16*)pqkv, nullptr, nullptr);

    // fused windowed attention
    attn_kernel<<<dim3(NHEAD, BWN), 256, ATTN_SMEM>>>();

    // proj GEMM -> fp32 (window layout)
    gemm2<0><<<dim3(1, TOKW / BM), 256, GEMM_SMEM>>>(TOKW, DIMC, DIMC,
        (const __nv_bfloat16*)pattn, (const __nv_bfloat16*)pwproj, projb,
        (float*)pproj, nullptr, nullptr, nullptr);

    // un-window + residual + LN2
    unwin_res_ln2_kernel<<<L_TOK / 8, 256>>>(x, n2w, n2b);

    // fc1 (+ exact GELU) -> bf16
    gemm2<2><<<dim3(4, (L_TOK + BM - 1) / BM), 256, GEMM_SMEM>>>(L_TOK, HID, DIMC,
        (const __nv_bfloat16*)ph2in, (const __nv_bfloat16*)pwfc1, fc1b,
        nullptr, (__nv_bfloat16*)ph2mid, nullptr, nullptr);

    // fc2 + residual -> d_out
    gemm2<3><<<dim3(1, (L_TOK + BM - 1) / BM), 256, GEMM_SMEM>>>(L_TOK, DIMC, HID,
        (const __nv_bfloat16*)ph2mid, (const __nv_bfloat16*)pwfc2, fc2b,
        nullptr, nullptr, (const float*)px1, out);
}

// round 3
// speedup vs baseline: 2.0384x; 1.6099x over previous
#include <cuda_runtime.h>
#include <cuda_bf16.h>
#include <math.h>
#include <stdint.h>

// ---------------- problem constants ----------------
#define L_TOK   131040          // 8*91*180
#define TOKW    138240          // 960 windows * 144 tokens
#define DIMC    192
#define HID     768
#define NHEAD   6
#define HDIM    32
#define NTOK    144             // tokens per window (2*6*12)
#define NWIN    64              // windows per lon-group (4*16)
#define NLON    15
#define BWN     960             // NLON*NWIN

// GEMM tiling
#define BM 128
#define BN 192
#define BK 32
#define GSTAGES 3
#define PADK 40
#define STAGE_ELEMS ((BM + BN) * PADK)   // 12800 elems, 25600 B
#define GEMM_SMEM (STAGE_ELEMS * 2 * GSTAGES)  // 76800 B

// ---------------- scratch buffers ----------------
__device__ __nv_bfloat16 g_A1[(size_t)TOKW * DIMC];
__device__ __nv_bfloat16 g_qkv[(size_t)TOKW * 3 * DIMC];
__device__ float         g_biasPre[(size_t)NHEAD * NWIN * NTOK * NTOK];
__device__ __nv_bfloat16 g_attnout[(size_t)TOKW * DIMC];
__device__ float         g_projout[(size_t)TOKW * DIMC];
__device__ float         g_x1[(size_t)L_TOK * DIMC];
__device__ __nv_bfloat16 g_h2in[(size_t)L_TOK * DIMC];
__device__ __nv_bfloat16 g_h2mid[(size_t)L_TOK * HID];
__device__ __nv_bfloat16 g_wqkv[3 * DIMC * DIMC];
__device__ __nv_bfloat16 g_wproj[DIMC * DIMC];
__device__ __nv_bfloat16 g_wfc1[HID * DIMC];
__device__ __nv_bfloat16 g_wfc2[DIMC * HID];

// ---------------- helpers ----------------
__global__ void f2bf_kernel(const float* __restrict__ s, __nv_bfloat16* __restrict__ d, int n) {
    int i = blockIdx.x * blockDim.x + threadIdx.x;
    if (i < n) d[i] = __float2bfloat16(s[i]);
}

__device__ __forceinline__ void cp_async16(uint32_t saddr, const void* gptr, bool pred) {
    int sz = pred ? 16 : 0;
    asm volatile("cp.async.cg.shared.global [%0], [%1], 16, %2;\n"
                 :: "r"(saddr), "l"(gptr), "r"(sz));
}

__device__ __forceinline__ void ldsm4(uint32_t* r, uint32_t addr) {
    asm volatile("ldmatrix.sync.aligned.m8n8.x4.shared.b16 {%0,%1,%2,%3}, [%4];\n"
                 : "=r"(r[0]), "=r"(r[1]), "=r"(r[2]), "=r"(r[3]) : "r"(addr));
}

__device__ __forceinline__ void mma16816(float* d, const uint32_t* a, const uint32_t* b) {
    asm volatile(
        "mma.sync.aligned.m16n8k16.row.col.f32.bf16.bf16.f32 "
        "{%0,%1,%2,%3}, {%4,%5,%6,%7}, {%8,%9}, {%0,%1,%2,%3};\n"
        : "+f"(d[0]), "+f"(d[1]), "+f"(d[2]), "+f"(d[3])
        : "r"(a[0]), "r"(a[1]), "r"(a[2]), "r"(a[3]), "r"(b[0]), "r"(b[1]));
}

__device__ __forceinline__ uint32_t packbf2(float lo, float hi) {
    __nv_bfloat162 p = __nv_bfloat162(__float2bfloat16(lo), __float2bfloat16(hi));
    return *reinterpret_cast<uint32_t*>(&p);
}

// ---------------- LN1 + pad + roll + window partition (warp per token) ----------------
__global__ __launch_bounds__(256) void ln1_window_kernel(const float* __restrict__ x,
                                                          const float* __restrict__ w,
                                                          const float* __restrict__ b) {
    int t = blockIdx.x * 8 + (threadIdx.x >> 5);   // window token [0, TOKW)
    int lane = threadIdx.x & 31;
    int bw = t / NTOK, n = t - bw * NTOK;
    int li = bw >> 6, wdw = bw & 63;
    int wp_i = n / 72, wa_i = (n / 12) % 6, wo_i = n % 12;
    int pl_p  = (wdw >> 4) * 2 + wp_i;
    int lat_p = (wdw & 15) * 6 + wa_i;
    int lon_p = li * 12 + wo_i;
    int pl_s  = (pl_p + 1) & 7;
    int lat_s = (lat_p + 3) % 96;
    int lon_s = (lon_p + 6) % 180;
    int lat_o = lat_s - 2;
    bool valid = (lat_o >= 0) && (lat_o < 91);
    size_t src = valid ? ((size_t)(pl_s * 91 + lat_o) * 180 + lon_s) * DIMC : 0;
    float v[6]; float s = 0.f, s2 = 0.f;
    #pragma unroll
    for (int k = 0; k < 6; k++) {
        float vv = valid ? x[src + lane + 32 * k] : 0.f;
        v[k] = vv; s += vv; s2 += vv * vv;
    }
    #pragma unroll
    for (int o = 16; o > 0; o >>= 1) {
        s  += __shfl_xor_sync(0xffffffffu, s, o);
        s2 += __shfl_xor_sync(0xffffffffu, s2, o);
    }
    float mean = s * (1.f / 192.f);
    float var  = s2 * (1.f / 192.f) - mean * mean;
    float rstd = rsqrtf(var + 1e-5f);
    #pragma unroll
    for (int k = 0; k < 6; k++) {
        int c = lane + 32 * k;
        float h = valid ? (v[k] - mean) * rstd * w[c] + b[c] : 0.f;
        g_A1[(size_t)t * DIMC + c] = __float2bfloat16(h);
    }
}

// ---------------- earth position bias precompute: [head][w][i][j] ----------------
__global__ __launch_bounds__(256) void bias_pre_kernel(const float* __restrict__ btab) {
    int hw = blockIdx.x;                 // head*NWIN + wdw
    int head = hw / NWIN, wdw = hw % NWIN;
    int base2 = wdw * NHEAD + head;
    float* dst = g_biasPre + (size_t)hw * NTOK * NTOK;
    for (int e = threadIdx.x; e < NTOK * NTOK; e += 256) {
        int i = e / NTOK, j = e - i * NTOK;
        int zi = i / 72, hi = (i / 12) % 6, wi = i % 12;
        int zj = j / 72, hj = (j / 12) % 6, wj = j % 12;
        int bidx = (zi + 2 * zj) * 828 + (hi + 6 * hj) * 23 + (wi - wj + 11);
        dst[e] = btab[(size_t)bidx * (NWIN * NHEAD) + base2];
    }
}

// ---------------- bf16 GEMM v3: 512 threads, cp.async + ldmatrix, 128x192 tile ----------------
// MODE 0: fp32 out + bias    MODE 1: bf16 out + bias
// MODE 2: gelu(acc+bias) -> bf16     MODE 3: Out = X1 + acc + bias (fp32)
template <int MODE>
__global__ __launch_bounds__(512, 1) void gemm2(
    int M, int N, int K,
    const __nv_bfloat16* __restrict__ A,
    const __nv_bfloat16* __restrict__ Bw,
    const float* __restrict__ bias,
    float* __restrict__ Cf,
    __nv_bfloat16* __restrict__ Cb,
    const float* __restrict__ X1,
    float* __restrict__ Out) {
    extern __shared__ __align__(16) unsigned char smraw[];
    uint32_t smem_u32 = (uint32_t)__cvta_generic_to_shared(smraw);

    const int tid = threadIdx.x;
    const int lane = tid & 31, warp = tid >> 5;
    const int m0 = blockIdx.y * BM;
    const int n0 = blockIdx.x * BN;
    const int wm = (warp >> 2) * 32;   // 4 warp rows * 32
    const int wn = (warp & 3) * 48;    // 4 warp cols * 48
    const int KT = K >> 5;

    float acc[2][6][4];
    #pragma unroll
    for (int a = 0; a < 2; a++)
        #pragma unroll
        for (int b2 = 0; b2 < 6; b2++)
            #pragma unroll
            for (int c = 0; c < 4; c++) acc[a][b2][c] = 0.f;

    auto load_stage = [&](int stage, int kt) {
        const int kb = kt << 5;
        uint32_t sbase = smem_u32 + stage * (STAGE_ELEMS * 2);
        {   // A: 128 rows x 32 cols = 512 uint4
            int row = tid >> 2, col = (tid & 3) << 3;
            int gr = m0 + row;
            bool p = gr < M;
            const __nv_bfloat16* gp = A + (size_t)(p ? gr : 0) * K + kb + col;
            cp_async16(sbase + (uint32_t)(row * PADK + col) * 2, gp, p);
        }
        uint32_t bbase = sbase + BM * PADK * 2;
        {   // B: 192 rows x 32 cols = 768 uint4
            int row = tid >> 2, col = (tid & 3) << 3;
            const __nv_bfloat16* gp = Bw + (size_t)(n0 + row) * K + kb + col;
            cp_async16(bbase + (uint32_t)(row * PADK + col) * 2, gp, true);
            int c = tid + 512;
            if (c < 768) {
                int row2 = c >> 2, col2 = (c & 3) << 3;
                const __nv_bfloat16* gp2 = Bw + (size_t)(n0 + row2) * K + kb + col2;
                cp_async16(bbase + (uint32_t)(row2 * PADK + col2) * 2, gp2, true);
            }
        }
    };

    #pragma unroll
    for (int s = 0; s < GSTAGES - 1; s++) {
        load_stage(s, s);
        asm volatile("cp.async.commit_group;\n");
    }

    for (int kt = 0; kt < KT; kt++) {
        asm volatile("cp.async.wait_group 1;\n");
        __syncthreads();
        uint32_t sbase = smem_u32 + (kt % GSTAGES) * (STAGE_ELEMS * 2);
        #pragma unroll
        for (int kk = 0; kk < 32; kk += 16) {
            uint32_t af[2][4], bfr[3][4];
            #pragma unroll
            for (int mi = 0; mi < 2; mi++) {
                uint32_t addr = sbase +
                    (uint32_t)(((wm + mi * 16 + (lane & 15)) * PADK) + kk + ((lane & 16) >> 1)) * 2;
                ldsm4(af[mi], addr);
            }
            #pragma unroll
            for (int nb = 0; nb < 3; nb++) {
                int nr = wn + nb * 16 + (lane & 7) + ((lane & 16) >> 1);
                uint32_t addr = sbase + BM * PADK * 2 +
                    (uint32_t)(nr * PADK + kk + (lane & 8)) * 2;
                ldsm4(bfr[nb], addr);
            }
            #pragma unroll
            for (int mi = 0; mi < 2; mi++)
                #pragma unroll
                for (int ni = 0; ni < 6; ni++)
                    mma16816(acc[mi][ni], af[mi], &bfr[ni >> 1][(ni & 1) * 2]);
        }
        int kn = kt + GSTAGES - 1;
        if (kn < KT) load_stage(kn % GSTAGES, kn);
        asm volatile("cp.async.commit_group;\n");
    }

    // epilogue
    const int g = lane >> 2, c4 = lane & 3;
    #pragma unroll
    for (int mi = 0; mi < 2; mi++) {
        #pragma unroll
        for (int ni = 0; ni < 6; ni++) {
            int row0 = m0 + wm + mi * 16 + g;
            int col0 = n0 + wn + ni * 8 + 2 * c4;
            float2 bv = *(const float2*)(bias + col0);
            #pragma unroll
            for (int rr = 0; rr < 2; rr++) {
                int row = row0 + rr * 8;
                if (row >= M) continue;
                float v0 = acc[mi][ni][rr * 2 + 0] + bv.x;
                float v1 = acc[mi][ni][rr * 2 + 1] + bv.y;
                size_t off = (size_t)row * N + col0;
                if (MODE == 0) {
                    *(float2*)(Cf + off) = make_float2(v0, v1);
                } else if (MODE == 1) {
                    *(__nv_bfloat162*)(Cb + off) =
                        __nv_bfloat162(__float2bfloat16(v0), __float2bfloat16(v1));
                } else if (MODE == 2) {
                    float g0 = 0.5f * v0 * (1.0f + erff(v0 * 0.70710678118654752f));
                    float g1 = 0.5f * v1 * (1.0f + erff(v1 * 0.70710678118654752f));
                    *(__nv_bfloat162*)(Cb + off) =
                        __nv_bfloat162(__float2bfloat16(g0), __float2bfloat16(g1));
                } else {
                    float2 xv = *(const float2*)(X1 + off);
                    *(float2*)(Out + off) = make_float2(xv.x + v0, xv.y + v1);
                }
            }
        }
    }
}

// ---------------- tensor-core windowed attention ----------------
// one block = one (window, head); 9 warps, each warp owns a 16-row M tile.
#define APAD 40     // q/k row stride (halves)
#define VPAD 152    // v^T row stride (halves)

__global__ __launch_bounds__(288, 1) void attn_kernel() {
    const int head = blockIdx.x;
    const int bw = blockIdx.y;
    const int li = bw / NWIN;
    const int wdw = bw - li * NWIN;
    const int tid = threadIdx.x;
    const int lane = tid & 31;
    const int warp = tid >> 5;        // 0..8

    __shared__ __align__(16) __nv_bfloat16 sq[NTOK * APAD];
    __shared__ __align__(16) __nv_bfloat16 sk[NTOK * APAD];
    __shared__ __align__(16) __nv_bfloat16 svt[HDIM * VPAD];
    __shared__ int sreg[NTOK];

    const float qscale = 0.17677669529663687f;   // 1/sqrt(32)
    for (int idx = tid; idx < NTOK * HDIM; idx += 288) {
        int j = idx >> 5, d = idx & 31;
        size_t base = (size_t)(bw * NTOK + j) * (3 * DIMC) + head * HDIM + d;
        sq[j * APAD + d] = __float2bfloat16(__bfloat162float(g_qkv[base]) * qscale);
        sk[j * APAD + d] = g_qkv[base + DIMC];
        svt[d * VPAD + j] = g_qkv[base + 2 * DIMC];
    }
    if (tid < NTOK) {
        int n = tid;
        int wp_i = n / 72, wa_i = (n / 12) % 6, wo_i = n % 12;
        int pl_p  = (wdw >> 4) * 2 + wp_i;
        int lat_p = (wdw & 15) * 6 + wa_i;
        int lon_p = li * 12 + wo_i;
        int rpl  = pl_p  < 6  ? 0 : (pl_p  < 7  ? 1 : 2);
        int rlat = lat_p < 90 ? 0 : (lat_p < 93 ? 1 : 2);
        int rlon = lon_p < 174 ? 0 : 1;
        sreg[tid] = (rpl * 3 + rlat) * 3 + rlon;
    }
    __syncthreads();

    uint32_t sq_u = (uint32_t)__cvta_generic_to_shared(sq);
    uint32_t sk_u = (uint32_t)__cvta_generic_to_shared(sk);
    uint32_t sv_u = (uint32_t)__cvta_generic_to_shared(svt);

    const int qrow0 = warp * 16;
    const int g = lane >> 2, c4 = lane & 3;

    // Q fragments (2 k-steps)
    uint32_t aq[2][4];
    #pragma unroll
    for (int kkidx = 0; kkidx < 2; kkidx++) {
        uint32_t addr = sq_u +
            (uint32_t)((qrow0 + (lane & 15)) * APAD + kkidx * 16 + ((lane & 16) >> 1)) * 2;
        ldsm4(aq[kkidx], addr);
    }

    // S = Q K^T : 18 n8 tiles
    float sacc[18][4];
    #pragma unroll
    for (int t = 0; t < 18; t++)
        #pragma unroll
        for (int c = 0; c < 4; c++) sacc[t][c] = 0.f;

    #pragma unroll
    for (int nt = 0; nt < 9; nt++) {
        #pragma unroll
        for (int kkidx = 0; kkidx < 2; kkidx++) {
            uint32_t bk[4];
            uint32_t addr = sk_u +
                (uint32_t)((nt * 16 + (lane & 7) + ((lane & 16) >> 1)) * APAD
                           + kkidx * 16 + (lane & 8)) * 2;
            ldsm4(bk, addr);
            mma16816(sacc[2 * nt],     aq[kkidx], &bk[0]);
            mma16816(sacc[2 * nt + 1], aq[kkidx], &bk[2]);
        }
    }

    // bias + mask
    const int row0 = qrow0 + g, row1 = row0 + 8;
    const float* bb = g_biasPre + (size_t)(head * NWIN + wdw) * NTOK * NTOK;
    const int rg0 = sreg[row0], rg1 = sreg[row1];
    #pragma unroll
    for (int t = 0; t < 18; t++) {
        int col = t * 8 + 2 * c4;
        float2 b0 = *(const float2*)(bb + (size_t)row0 * NTOK + col);
        float2 b1 = *(const float2*)(bb + (size_t)row1 * NTOK + col);
        int rc0 = sreg[col], rc1 = sreg[col + 1];
        sacc[t][0] += b0.x + (rc0 != rg0 ? -100.f : 0.f);
        sacc[t][1] += b0.y + (rc1 != rg0 ? -100.f : 0.f);
        sacc[t][2] += b1.x + (rc0 != rg1 ? -100.f : 0.f);
        sacc[t][3] += b1.y + (rc1 != rg1 ? -100.f : 0.f);
    }

    // softmax (rows g and g+8); reduce over the 4 lanes of the quad (xor 1,2)
    float mx0 = -1e30f, mx1 = -1e30f;
    #pragma unroll
    for (int t = 0; t < 18; t++) {
        mx0 = fmaxf(mx0, fmaxf(sacc[t][0], sacc[t][1]));
        mx1 = fmaxf(mx1, fmaxf(sacc[t][2], sacc[t][3]));
    }
    #pragma unroll
    for (int o = 1; o <= 2; o <<= 1) {
        mx0 = fmaxf(mx0, __shfl_xor_sync(0xffffffffu, mx0, o));
        mx1 = fmaxf(mx1, __shfl_xor_sync(0xffffffffu, mx1, o));
    }
    float sum0 = 0.f, sum1 = 0.f;
    #pragma unroll
    for (int t = 0; t < 18; t++) {
        sacc[t][0] = __expf(sacc[t][0] - mx0);
        sacc[t][1] = __expf(sacc[t][1] - mx0);
        sacc[t][2] = __expf(sacc[t][2] - mx1);
        sacc[t][3] = __expf(sacc[t][3] - mx1);
        sum0 += sacc[t][0] + sacc[t][1];
        sum1 += sacc[t][2] + sacc[t][3];
    }
    #pragma unroll
    for (int o = 1; o <= 2; o <<= 1) {
        sum0 += __shfl_xor_sync(0xffffffffu, sum0, o);
        sum1 += __shfl_xor_sync(0xffffffffu, sum1, o);
    }
    float inv0 = 1.f / sum0, inv1 = 1.f / sum1;

    // pack P (unnormalized exp) into A fragments: kt covers j in [16kt, 16kt+16)
    uint32_t ap[9][4];
    #pragma unroll
    for (int kt = 0; kt < 9; kt++) {
        ap[kt][0] = packbf2(sacc[2 * kt][0],     sacc[2 * kt][1]);
        ap[kt][1] = packbf2(sacc[2 * kt][2],     sacc[2 * kt][3]);
        ap[kt][2] = packbf2(sacc[2 * kt + 1][0], sacc[2 * kt + 1][1]);
        ap[kt][3] = packbf2(sacc[2 * kt + 1][2], sacc[2 * kt + 1][3]);
    }

    // O = P V : V^T stored [d][j], 4 n8 d-tiles
    float oacc[4][4];
    #pragma unroll
    for (int t = 0; t < 4; t++)
        #pragma unroll
        for (int c = 0; c < 4; c++) oacc[t][c] = 0.f;

    #pragma unroll
    for (int kt = 0; kt < 9; kt++) {
        #pragma unroll
        for (int dh = 0; dh < 2; dh++) {
            uint32_t bv[4];
            uint32_t addr = sv_u +
                (uint32_t)((dh * 16 + (lane & 7) + ((lane & 16) >> 1)) * VPAD
                           + kt * 16 + (lane & 8)) * 2;
            ldsm4(bv, addr);
            mma16816(oacc[2 * dh],     ap[kt], &bv[0]);
            mma16816(oacc[2 * dh + 1], ap[kt], &bv[2]);
        }
    }

    // epilogue: scale rows by inv, write bf16
    #pragma unroll
    for (int dt = 0; dt < 4; dt++) {
        int col = head * HDIM + dt * 8 + 2 * c4;
        size_t t0 = (size_t)(bw * NTOK + row0) * DIMC + col;
        size_t t1 = (size_t)(bw * NTOK + row1) * DIMC + col;
        *(__nv_bfloat162*)(g_attnout + t0) =
            __nv_bfloat162(__float2bfloat16(oacc[dt][0] * inv0), __float2bfloat16(oacc[dt][1] * inv0));
        *(__nv_bfloat162*)(g_attnout + t1) =
            __nv_bfloat162(__float2bfloat16(oacc[dt][2] * inv1), __float2bfloat16(oacc[dt][3] * inv1));
    }
}

// ---------------- un-window + residual + LN2 (warp per token) ----------------
__global__ __launch_bounds__(256) void unwin_res_ln2_kernel(const float* __restrict__ x,
                                                             const float* __restrict__ w,
                                                             const float* __restrict__ b) {
    int t = blockIdx.x * 8 + (threadIdx.x >> 5);   // [0, L_TOK)
    int lane = threadIdx.x & 31;
    int pl = t / (91 * 180);
    int rem = t - pl * (91 * 180);
    int lat = rem / 180, lon = rem % 180;
    int pl_p  = (pl + 7) & 7;
    int lat_p = (lat + 95) % 96;
    int lon_p = (lon + 174) % 180;
    int plg = pl_p >> 1, wp_i = pl_p & 1;
    int latg = lat_p / 6, wa_i = lat_p % 6;
    int li = lon_p / 12, wo_i = lon_p % 12;
    int wdw = plg * 16 + latg;
    int n = (wp_i * 6 + wa_i) * 12 + wo_i;
    size_t slot = ((size_t)((li * NWIN + wdw) * NTOK + n)) * DIMC;
    size_t base = (size_t)t * DIMC;
    float v[6]; float s = 0.f, s2 = 0.f;
    #pragma unroll
    for (int k = 0; k < 6; k++) {
        int c = lane + 32 * k;
        float vv = x[base + c] + g_projout[slot + c];
        v[k] = vv; s += vv; s2 += vv * vv;
        g_x1[base + c] = vv;
    }
    #pragma unroll
    for (int o = 16; o > 0; o >>= 1) {
        s  += __shfl_xor_sync(0xffffffffu, s, o);
        s2 += __shfl_xor_sync(0xffffffffu, s2, o);
    }
    float mean = s * (1.f / 192.f);
    float var  = s2 * (1.f / 192.f) - mean * mean;
    float rstd = rsqrtf(var + 1e-5f);
    #pragma unroll
    for (int k = 0; k < 6; k++) {
        int c = lane + 32 * k;
        float h = (v[k] - mean) * rstd * w[c] + b[c];
        g_h2in[base + c] = __float2bfloat16(h);
    }
}

// ---------------- launch ----------------
extern "C" void kernel_launch(void* const* d_in, const int* in_sizes, int n_in,
                              void* d_out, int out_size) {
    const float* x     = (const float*)d_in[0];
    const float* n1w   = (const float*)d_in[1];
    const float* n1b   = (const float*)d_in[2];
    const float* qkvw  = (const float*)d_in[3];
    const float* qkvb  = (const float*)d_in[4];
    const float* btab  = (const float*)d_in[5];
    const float* projw = (const float*)d_in[6];
    const float* projb = (const float*)d_in[7];
    const float* n2w   = (const float*)d_in[8];
    const float* n2b   = (const float*)d_in[9];
    const float* fc1w  = (const float*)d_in[10];
    const float* fc1b  = (const float*)d_in[11];
    const float* fc2w  = (const float*)d_in[12];
    const float* fc2b  = (const float*)d_in[13];
    float* out = (float*)d_out;

    void *pA1, *pqkv, *pattn, *pproj, *px1, *ph2in, *ph2mid;
    void *pwqkv, *pwproj, *pwfc1, *pwfc2;
    cudaGetSymbolAddress(&pA1, g_A1);
    cudaGetSymbolAddress(&pqkv, g_qkv);
    cudaGetSymbolAddress(&pattn, g_attnout);
    cudaGetSymbolAddress(&pproj, g_projout);
    cudaGetSymbolAddress(&px1, g_x1);
    cudaGetSymbolAddress(&ph2in, g_h2in);
    cudaGetSymbolAddress(&ph2mid, g_h2mid);
    cudaGetSymbolAddress(&pwqkv, g_wqkv);
    cudaGetSymbolAddress(&pwproj, g_wproj);
    cudaGetSymbolAddress(&pwfc1, g_wfc1);
    cudaGetSymbolAddress(&pwfc2, g_wfc2);

    cudaFuncSetAttribute(gemm2<0>, cudaFuncAttributeMaxDynamicSharedMemorySize, GEMM_SMEM);
    cudaFuncSetAttribute(gemm2<1>, cudaFuncAttributeMaxDynamicSharedMemorySize, GEMM_SMEM);
    cudaFuncSetAttribute(gemm2<2>, cudaFuncAttributeMaxDynamicSharedMemorySize, GEMM_SMEM);
    cudaFuncSetAttribute(gemm2<3>, cudaFuncAttributeMaxDynamicSharedMemorySize, GEMM_SMEM);

    // 1: LN1 + window partition
    ln1_window_kernel<<<TOKW / 8, 256>>>(x, n1w, n1b);

    // 2-5: weight conversions (bf16)
    f2bf_kernel<<<(3 * DIMC * DIMC + 255) / 256, 256>>>(qkvw, (__nv_bfloat16*)pwqkv, 3 * DIMC * DIMC);
    f2bf_kernel<<<(DIMC * DIMC + 255) / 256, 256>>>(projw, (__nv_bfloat16*)pwproj, DIMC * DIMC);
    f2bf_kernel<<<(HID * DIMC + 255) / 256, 256>>>(fc1w, (__nv_bfloat16*)pwfc1, HID * DIMC);
    f2bf_kernel<<<(DIMC * HID + 255) / 256, 256>>>(fc2w, (__nv_bfloat16*)pwfc2, DIMC * HID);

    // 6: QKV GEMM -> bf16 (positioned for ncu -s 5 capture)
    gemm2<1><<<dim3(3, TOKW / BM), 512, GEMM_SMEM>>>(TOKW, 3 * DIMC, DIMC,
        (const __nv_bfloat16*)pA1, (const __nv_bfloat16*)pwqkv, qkvb,
        nullptr, (__nv_bfloat16*)pqkv, nullptr, nullptr);

    // 7: bias table precompute
    bias_pre_kernel<<<NHEAD * NWIN, 256>>>(btab);

    // 8: fused windowed attention (tensor core)
    attn_kernel<<<dim3(NHEAD, BWN), 288>>>();

    // 9: proj GEMM -> fp32 (window layout)
    gemm2<0><<<dim3(1, TOKW / BM), 512, GEMM_SMEM>>>(TOKW, DIMC, DIMC,
        (const __nv_bfloat16*)pattn, (const __nv_bfloat16*)pwproj, projb,
        (float*)pproj, nullptr, nullptr, nullptr);

    // 10: un-window + residual + LN2
    unwin_res_ln2_kernel<<<L_TOK / 8, 256>>>(x, n2w, n2b);

    // 11: fc1 (+ exact GELU) -> bf16
    gemm2<2><<<dim3(4, (L_TOK + BM - 1) / BM), 512, GEMM_SMEM>>>(L_TOK, HID, DIMC,
        (const __nv_bfloat16*)ph2in, (const __nv_bfloat16*)pwfc1, fc1b,
        nullptr, (__nv_bfloat16*)ph2mid, nullptr, nullptr);

    // 12: fc2 + residual -> d_out
    gemm2<3><<<dim3(1, (L_TOK + BM - 1) / BM), 512, GEMM_SMEM>>>(L_TOK, DIMC, HID,
        (const __nv_bfloat16*)ph2mid, (const __nv_bfloat16*)pwfc2, fc2b,
        nullptr, nullptr, (const float*)px1, out);
}

// round 5
// speedup vs baseline: 2.0563x; 1.0088x over previous
#include <cuda_runtime.h>
#include <cuda_bf16.h>
#include <math.h>
#include <stdint.h>

// ---------------- problem constants ----------------
#define L_TOK   131040          // 8*91*180
#define TOKW    138240          // 960 windows * 144 tokens
#define DIMC    192
#define HID     768
#define NHEAD   6
#define HDIM    32
#define NTOK    144             // tokens per window (2*6*12)
#define NWIN    64              // windows per lon-group (4*16)
#define NLON    15
#define BWN     960             // NLON*NWIN

// GEMM tiling
#define BM 128
#define BN 192
#define BK 32
#define GSTAGES 3
#define PADK 40
#define STAGE_ELEMS ((BM + BN) * PADK)   // 12800 elems, 25600 B
#define GEMM_SMEM (STAGE_ELEMS * 2 * GSTAGES)  // 76800 B

// ---------------- scratch buffers ----------------
__device__ __nv_bfloat16 g_A1[(size_t)TOKW * DIMC];
__device__ __nv_bfloat16 g_qkv[(size_t)TOKW * 3 * DIMC];
__device__ float         g_biasPre[(size_t)NHEAD * NWIN * NTOK * NTOK];
__device__ __nv_bfloat16 g_attnout[(size_t)TOKW * DIMC];
__device__ float         g_projout[(size_t)TOKW * DIMC];
__device__ float         g_x1[(size_t)L_TOK * DIMC];
__device__ __nv_bfloat16 g_h2in[(size_t)L_TOK * DIMC];
__device__ __nv_bfloat16 g_h2mid[(size_t)L_TOK * HID];
__device__ __nv_bfloat16 g_wqkv[3 * DIMC * DIMC];
__device__ __nv_bfloat16 g_wproj[DIMC * DIMC];
__device__ __nv_bfloat16 g_wfc1[HID * DIMC];
__device__ __nv_bfloat16 g_wfc2[DIMC * HID];

// ---------------- helpers ----------------
__global__ void f2bf_kernel(const float* __restrict__ s, __nv_bfloat16* __restrict__ d, int n) {
    int i = blockIdx.x * blockDim.x + threadIdx.x;
    if (i < n) d[i] = __float2bfloat16(s[i]);
}

__device__ __forceinline__ void cp_async16(uint32_t saddr, const void* gptr, bool pred) {
    int sz = pred ? 16 : 0;
    asm volatile("cp.async.cg.shared.global [%0], [%1], 16, %2;\n"
                 :: "r"(saddr), "l"(gptr), "r"(sz));
}

__device__ __forceinline__ void ldsm4(uint32_t* r, uint32_t addr) {
    asm volatile("ldmatrix.sync.aligned.m8n8.x4.shared.b16 {%0,%1,%2,%3}, [%4];\n"
                 : "=r"(r[0]), "=r"(r[1]), "=r"(r[2]), "=r"(r[3]) : "r"(addr));
}

__device__ __forceinline__ void mma16816(float* d, const uint32_t* a, const uint32_t* b) {
    asm volatile(
        "mma.sync.aligned.m16n8k16.row.col.f32.bf16.bf16.f32 "
        "{%0,%1,%2,%3}, {%4,%5,%6,%7}, {%8,%9}, {%0,%1,%2,%3};\n"
        : "+f"(d[0]), "+f"(d[1]), "+f"(d[2]), "+f"(d[3])
        : "r"(a[0]), "r"(a[1]), "r"(a[2]), "r"(a[3]), "r"(b[0]), "r"(b[1]));
}

__device__ __forceinline__ uint32_t packbf2(float lo, float hi) {
    __nv_bfloat162 p = __nv_bfloat162(__float2bfloat16(lo), __float2bfloat16(hi));
    return *reinterpret_cast<uint32_t*>(&p);
}

// ---------------- LN1 + pad + roll + window partition (warp per token) ----------------
__global__ __launch_bounds__(256) void ln1_window_kernel(const float* __restrict__ x,
                                                          const float* __restrict__ w,
                                                          const float* __restrict__ b) {
    int t = blockIdx.x * 8 + (threadIdx.x >> 5);
    int lane = threadIdx.x & 31;
    int bw = t / NTOK, n = t - bw * NTOK;
    int li = bw >> 6, wdw = bw & 63;
    int wp_i = n / 72, wa_i = (n / 12) % 6, wo_i = n % 12;
    int pl_p  = (wdw >> 4) * 2 + wp_i;
    int lat_p = (wdw & 15) * 6 + wa_i;
    int lon_p = li * 12 + wo_i;
    int pl_s  = (pl_p + 1) & 7;
    int lat_s = (lat_p + 3) % 96;
    int lon_s = (lon_p + 6) % 180;
    int lat_o = lat_s - 2;
    bool valid = (lat_o >= 0) && (lat_o < 91);
    size_t src = valid ? ((size_t)(pl_s * 91 + lat_o) * 180 + lon_s) * DIMC : 0;
    float v[6]; float s = 0.f, s2 = 0.f;
    #pragma unroll
    for (int k = 0; k < 6; k++) {
        float vv = valid ? x[src + lane + 32 * k] : 0.f;
        v[k] = vv; s += vv; s2 += vv * vv;
    }
    #pragma unroll
    for (int o = 16; o > 0; o >>= 1) {
        s  += __shfl_xor_sync(0xffffffffu, s, o);
        s2 += __shfl_xor_sync(0xffffffffu, s2, o);
    }
    float mean = s * (1.f / 192.f);
    float var  = s2 * (1.f / 192.f) - mean * mean;
    float rstd = rsqrtf(var + 1e-5f);
    #pragma unroll
    for (int k = 0; k < 6; k++) {
        int c = lane + 32 * k;
        float h = valid ? (v[k] - mean) * rstd * w[c] + b[c] : 0.f;
        g_A1[(size_t)t * DIMC + c] = __float2bfloat16(h);
    }
}

// ---------------- earth position bias precompute ----------------
__global__ __launch_bounds__(256) void bias_pre_kernel(const float* __restrict__ btab) {
    int hw = blockIdx.x;
    int head = hw / NWIN, wdw = hw % NWIN;
    int base2 = wdw * NHEAD + head;
    float* dst = g_biasPre + (size_t)hw * NTOK * NTOK;
    for (int e = threadIdx.x; e < NTOK * NTOK; e += 256) {
        int i = e / NTOK, j = e - i * NTOK;
        int zi = i / 72, hi = (i / 12) % 6, wi = i % 12;
        int zj = j / 72, hj = (j / 12) % 6, wj = j % 12;
        int bidx = (zi + 2 * zj) * 828 + (hi + 6 * hj) * 23 + (wi - wj + 11);
        dst[e] = btab[(size_t)bidx * (NWIN * NHEAD) + base2];
    }
}

// ---------------- bf16 GEMM v4: 256 thr, warp tile 64x48, loads-first pipeline ------------
// MODE 0: fp32 out + bias    MODE 1: bf16 out + bias
// MODE 2: gelu(acc+bias) -> bf16     MODE 3: Out = X1 + acc + bias (fp32)
template <int MODE>
__global__ __launch_bounds__(256, 1) void gemm2(
    int M, int N, int K,
    const __nv_bfloat16* __restrict__ A,
    const __nv_bfloat16* __restrict__ Bw,
    const float* __restrict__ bias,
    float* __restrict__ Cf,
    __nv_bfloat16* __restrict__ Cb,
    const float* __restrict__ X1,
    float* __restrict__ Out) {
    extern __shared__ __align__(16) unsigned char smraw[];
    uint32_t smem_u32 = (uint32_t)__cvta_generic_to_shared(smraw);

    const int tid = threadIdx.x;
    const int lane = tid & 31, warp = tid >> 5;
    const int m0 = blockIdx.y * BM;
    const int n0 = blockIdx.x * BN;
    const int wm = (warp >> 2) * 64;   // 2 warp rows * 64
    const int wn = (warp & 3) * 48;    // 4 warp cols * 48
    const int KT = K >> 5;

    float acc[4][6][4];
    #pragma unroll
    for (int a = 0; a < 4; a++)
        #pragma unroll
        for (int b2 = 0; b2 < 6; b2++)
            #pragma unroll
            for (int c = 0; c < 4; c++) acc[a][b2][c] = 0.f;

    auto load_stage = [&](int stage, int kt) {
        const int kb = kt << 5;
        uint32_t sbase = smem_u32 + stage * (STAGE_ELEMS * 2);
        #pragma unroll
        for (int it = 0; it < 2; it++) {   // A: 512 uint4
            int q = tid + it * 256;
            int row = q >> 2, col = (q & 3) << 3;
            int gr = m0 + row;
            bool p = gr < M;
            const __nv_bfloat16* gp = A + (size_t)(p ? gr : 0) * K + kb + col;
            cp_async16(sbase + (uint32_t)(row * PADK + col) * 2, gp, p);
        }
        uint32_t bbase = sbase + BM * PADK * 2;
        #pragma unroll
        for (int it = 0; it < 3; it++) {   // B: 768 uint4
            int q = tid + it * 256;
            int row = q >> 2, col = (q & 3) << 3;
            const __nv_bfloat16* gp = Bw + (size_t)(n0 + row) * K + kb + col;
            cp_async16(bbase + (uint32_t)(row * PADK + col) * 2, gp, true);
        }
    };

    #pragma unroll
    for (int s = 0; s < GSTAGES - 1; s++) {
        load_stage(s, s);
        asm volatile("cp.async.commit_group;\n");
    }

    for (int kt = 0; kt < KT; kt++) {
        asm volatile("cp.async.wait_group 1;\n");
        __syncthreads();
        // issue next-stage loads FIRST so LDGSTS flight overlaps the MMAs below
        int kn = kt + GSTAGES - 1;
        if (kn < KT) {
            load_stage(kn % GSTAGES, kn);
        }
        asm volatile("cp.async.commit_group;\n");

        uint32_t sbase = smem_u32 + (kt % GSTAGES) * (STAGE_ELEMS * 2);
        #pragma unroll
        for (int kk = 0; kk < 32; kk += 16) {
            uint32_t af[4][4], bfr[3][4];
            #pragma unroll
            for (int mi = 0; mi < 4; mi++) {
                uint32_t addr = sbase +
                    (uint32_t)(((wm + mi * 16 + (lane & 15)) * PADK) + kk + ((lane & 16) >> 1)) * 2;
                ldsm4(af[mi], addr);
            }
            #pragma unroll
            for (int nb = 0; nb < 3; nb++) {
                int nr = wn + nb * 16 + (lane & 7) + ((lane & 16) >> 1);
                uint32_t addr = sbase + BM * PADK * 2 +
                    (uint32_t)(nr * PADK + kk + (lane & 8)) * 2;
                ldsm4(bfr[nb], addr);
            }
            #pragma unroll
            for (int mi = 0; mi < 4; mi++)
                #pragma unroll
                for (int ni = 0; ni < 6; ni++)
                    mma16816(acc[mi][ni], af[mi], &bfr[ni >> 1][(ni & 1) * 2]);
        }
    }

    // epilogue
    const int g = lane >> 2, c4 = lane & 3;
    #pragma unroll
    for (int mi = 0; mi < 4; mi++) {
        #pragma unroll
        for (int ni = 0; ni < 6; ni++) {
            int row0 = m0 + wm + mi * 16 + g;
            int col0 = n0 + wn + ni * 8 + 2 * c4;
            float2 bv = *(const float2*)(bias + col0);
            #pragma unroll
            for (int rr = 0; rr < 2; rr++) {
                int row = row0 + rr * 8;
                if (row >= M) continue;
                float v0 = acc[mi][ni][rr * 2 + 0] + bv.x;
                float v1 = acc[mi][ni][rr * 2 + 1] + bv.y;
                size_t off = (size_t)row * N + col0;
                if (MODE == 0) {
                    *(float2*)(Cf + off) = make_float2(v0, v1);
                } else if (MODE == 1) {
                    *(__nv_bfloat162*)(Cb + off) =
                        __nv_bfloat162(__float2bfloat16(v0), __float2bfloat16(v1));
                } else if (MODE == 2) {
                    float g0 = 0.5f * v0 * (1.0f + erff(v0 * 0.70710678118654752f));
                    float g1 = 0.5f * v1 * (1.0f + erff(v1 * 0.70710678118654752f));
                    *(__nv_bfloat162*)(Cb + off) =
                        __nv_bfloat162(__float2bfloat16(g0), __float2bfloat16(g1));
                } else {
                    float2 xv = *(const float2*)(X1 + off);
                    *(float2*)(Out + off) = make_float2(xv.x + v0, xv.y + v1);
                }
            }
        }
    }
}

// ---------------- tensor-core windowed attention ----------------
#define APAD 40
#define VPAD 152

__global__ __launch_bounds__(288, 1) void attn_kernel() {
    const int head = blockIdx.x;
    const int bw = blockIdx.y;
    const int li = bw / NWIN;
    const int wdw = bw - li * NWIN;
    const int tid = threadIdx.x;
    const int lane = tid & 31;
    const int warp = tid >> 5;

    __shared__ __align__(16) __nv_bfloat16 sq[NTOK * APAD];
    __shared__ __align__(16) __nv_bfloat16 sk[NTOK * APAD];
    __shared__ __align__(16) __nv_bfloat16 svt[HDIM * VPAD];
    __shared__ int sreg[NTOK];

    const float qscale = 0.17677669529663687f;
    for (int idx = tid; idx < NTOK * HDIM; idx += 288) {
        int j = idx >> 5, d = idx & 31;
        size_t base = (size_t)(bw * NTOK + j) * (3 * DIMC) + head * HDIM + d;
        sq[j * APAD + d] = __float2bfloat16(__bfloat162float(g_qkv[base]) * qscale);
        sk[j * APAD + d] = g_qkv[base + DIMC];
        svt[d * VPAD + j] = g_qkv[base + 2 * DIMC];
    }
    if (tid < NTOK) {
        int n = tid;
        int wp_i = n / 72, wa_i = (n / 12) % 6, wo_i = n % 12;
        int pl_p  = (wdw >> 4) * 2 + wp_i;
        int lat_p = (wdw & 15) * 6 + wa_i;
        int lon_p = li * 12 + wo_i;
        int rpl  = pl_p  < 6  ? 0 : (pl_p  < 7  ? 1 : 2);
        int rlat = lat_p < 90 ? 0 : (lat_p < 93 ? 1 : 2);
        int rlon = lon_p < 174 ? 0 : 1;
        sreg[tid] = (rpl * 3 + rlat) * 3 + rlon;
    }
    __syncthreads();

    uint32_t sq_u = (uint32_t)__cvta_generic_to_shared(sq);
    uint32_t sk_u = (uint32_t)__cvta_generic_to_shared(sk);
    uint32_t sv_u = (uint32_t)__cvta_generic_to_shared(svt);

    const int qrow0 = warp * 16;
    const int g = lane >> 2, c4 = lane & 3;

    uint32_t aq[2][4];
    #pragma unroll
    for (int kkidx = 0; kkidx < 2; kkidx++) {
        uint32_t addr = sq_u +
            (uint32_t)((qrow0 + (lane & 15)) * APAD + kkidx * 16 + ((lane & 16) >> 1)) * 2;
        ldsm4(aq[kkidx], addr);
    }

    float sacc[18][4];
    #pragma unroll
    for (int t = 0; t < 18; t++)
        #pragma unroll
        for (int c = 0; c < 4; c++) sacc[t][c] = 0.f;

    #pragma unroll
    for (int nt = 0; nt < 9; nt++) {
        #pragma unroll
        for (int kkidx = 0; kkidx < 2; kkidx++) {
            uint32_t bk[4];
            uint32_t addr = sk_u +
                (uint32_t)((nt * 16 + (lane & 7) + ((lane & 16) >> 1)) * APAD
                           + kkidx * 16 + (lane & 8)) * 2;
            ldsm4(bk, addr);
            mma16816(sacc[2 * nt],     aq[kkidx], &bk[0]);
            mma16816(sacc[2 * nt + 1], aq[kkidx], &bk[2]);
        }
    }

    const int row0 = qrow0 + g, row1 = row0 + 8;
    const float* bb = g_biasPre + (size_t)(head * NWIN + wdw) * NTOK * NTOK;
    const int rg0 = sreg[row0], rg1 = sreg[row1];
    #pragma unroll
    for (int t = 0; t < 18; t++) {
        int col = t * 8 + 2 * c4;
        float2 b0 = *(const float2*)(bb + (size_t)row0 * NTOK + col);
        float2 b1 = *(const float2*)(bb + (size_t)row1 * NTOK + col);
        int rc0 = sreg[col], rc1 = sreg[col + 1];
        sacc[t][0] += b0.x + (rc0 != rg0 ? -100.f : 0.f);
        sacc[t][1] += b0.y + (rc1 != rg0 ? -100.f : 0.f);
        sacc[t][2] += b1.x + (rc0 != rg1 ? -100.f : 0.f);
        sacc[t][3] += b1.y + (rc1 != rg1 ? -100.f : 0.f);
    }

    float mx0 = -1e30f, mx1 = -1e30f;
    #pragma unroll
    for (int t = 0; t < 18; t++) {
        mx0 = fmaxf(mx0, fmaxf(sacc[t][0], sacc[t][1]));
        mx1 = fmaxf(mx1, fmaxf(sacc[t][2], sacc[t][3]));
    }
    #pragma unroll
    for (int o = 1; o <= 2; o <<= 1) {
        mx0 = fmaxf(mx0, __shfl_xor_sync(0xffffffffu, mx0, o));
        mx1 = fmaxf(mx1, __shfl_xor_sync(0xffffffffu, mx1, o));
    }
    float sum0 = 0.f, sum1 = 0.f;
    #pragma unroll
    for (int t = 0; t < 18; t++) {
        sacc[t][0] = __expf(sacc[t][0] - mx0);
        sacc[t][1] = __expf(sacc[t][1] - mx0);
        sacc[t][2] = __expf(sacc[t][2] - mx1);
        sacc[t][3] = __expf(sacc[t][3] - mx1);
        sum0 += sacc[t][0] + sacc[t][1];
        sum1 += sacc[t][2] + sacc[t][3];
    }
    #pragma unroll
    for (int o = 1; o <= 2; o <<= 1) {
        sum0 += __shfl_xor_sync(0xffffffffu, sum0, o);
        sum1 += __shfl_xor_sync(0xffffffffu, sum1, o);
    }
    float inv0 = 1.f / sum0, inv1 = 1.f / sum1;

    uint32_t ap[9][4];
    #pragma unroll
    for (int kt = 0; kt < 9; kt++) {
        ap[kt][0] = packbf2(sacc[2 * kt][0],     sacc[2 * kt][1]);
        ap[kt][1] = packbf2(sacc[2 * kt][2],     sacc[2 * kt][3]);
        ap[kt][2] = packbf2(sacc[2 * kt + 1][0], sacc[2 * kt + 1][1]);
        ap[kt][3] = packbf2(sacc[2 * kt + 1][2], sacc[2 * kt + 1][3]);
    }

    float oacc[4][4];
    #pragma unroll
    for (int t = 0; t < 4; t++)
        #pragma unroll
        for (int c = 0; c < 4; c++) oacc[t][c] = 0.f;

    #pragma unroll
    for (int kt = 0; kt < 9; kt++) {
        #pragma unroll
        for (int dh = 0; dh < 2; dh++) {
            uint32_t bv[4];
            uint32_t addr = sv_u +
                (uint32_t)((dh * 16 + (lane & 7) + ((lane & 16) >> 1)) * VPAD
                           + kt * 16 + (lane & 8)) * 2;
            ldsm4(bv, addr);
            mma16816(oacc[2 * dh],     ap[kt], &bv[0]);
            mma16816(oacc[2 * dh + 1], ap[kt], &bv[2]);
        }
    }

    #pragma unroll
    for (int dt = 0; dt < 4; dt++) {
        int col = head * HDIM + dt * 8 + 2 * c4;
        size_t t0 = (size_t)(bw * NTOK + row0) * DIMC + col;
        size_t t1 = (size_t)(bw * NTOK + row1) * DIMC + col;
        *(__nv_bfloat162*)(g_attnout + t0) =
            __nv_bfloat162(__float2bfloat16(oacc[dt][0] * inv0), __float2bfloat16(oacc[dt][1] * inv0));
        *(__nv_bfloat162*)(g_attnout + t1) =
            __nv_bfloat162(__float2bfloat16(oacc[dt][2] * inv1), __float2bfloat16(oacc[dt][3] * inv1));
    }
}

// ---------------- un-window + residual + LN2 (warp per token) ----------------
__global__ __launch_bounds__(256) void unwin_res_ln2_kernel(const float* __restrict__ x,
                                                             const float* __restrict__ w,
                                                             const float* __restrict__ b) {
    int t = blockIdx.x * 8 + (threadIdx.x >> 5);
    int lane = threadIdx.x & 31;
    int pl = t / (91 * 180);
    int rem = t - pl * (91 * 180);
    int lat = rem / 180, lon = rem % 180;
    int pl_p  = (pl + 7) & 7;
    int lat_p = (lat + 95) % 96;
    int lon_p = (lon + 174) % 180;
    int plg = pl_p >> 1, wp_i = pl_p & 1;
    int latg = lat_p / 6, wa_i = lat_p % 6;
    int li = lon_p / 12, wo_i = lon_p % 12;
    int wdw = plg * 16 + latg;
    int n = (wp_i * 6 + wa_i) * 12 + wo_i;
    size_t slot = ((size_t)((li * NWIN + wdw) * NTOK + n)) * DIMC;
    size_t base = (size_t)t * DIMC;
    float v[6]; float s = 0.f, s2 = 0.f;
    #pragma unroll
    for (int k = 0; k < 6; k++) {
        int c = lane + 32 * k;
        float vv = x[base + c] + g_projout[slot + c];
        v[k] = vv; s += vv; s2 += vv * vv;
        g_x1[base + c] = vv;
    }
    #pragma unroll
    for (int o = 16; o > 0; o >>= 1) {
        s  += __shfl_xor_sync(0xffffffffu, s, o);
        s2 += __shfl_xor_sync(0xffffffffu, s2, o);
    }
    float mean = s * (1.f / 192.f);
    float var  = s2 * (1.f / 192.f) - mean * mean;
    float rstd = rsqrtf(var + 1e-5f);
    #pragma unroll
    for (int k = 0; k < 6; k++) {
        int c = lane + 32 * k;
        float h = (v[k] - mean) * rstd * w[c] + b[c];
        g_h2in[base + c] = __float2bfloat16(h);
    }
}

// ---------------- launch ----------------
extern "C" void kernel_launch(void* const* d_in, const int* in_sizes, int n_in,
                              void* d_out, int out_size) {
    const float* x     = (const float*)d_in[0];
    const float* n1w   = (const float*)d_in[1];
    const float* n1b   = (const float*)d_in[2];
    const float* qkvw  = (const float*)d_in[3];
    const float* qkvb  = (const float*)d_in[4];
    const float* btab  = (const float*)d_in[5];
    const float* projw = (const float*)d_in[6];
    const float* projb = (const float*)d_in[7];
    const float* n2w   = (const float*)d_in[8];
    const float* n2b   = (const float*)d_in[9];
    const float* fc1w  = (const float*)d_in[10];
    const float* fc1b  = (const float*)d_in[11];
    const float* fc2w  = (const float*)d_in[12];
    const float* fc2b  = (const float*)d_in[13];
    float* out = (float*)d_out;

    void *pA1, *pqkv, *pattn, *pproj, *px1, *ph2in, *ph2mid;
    void *pwqkv, *pwproj, *pwfc1, *pwfc2;
    cudaGetSymbolAddress(&pA1, g_A1);
    cudaGetSymbolAddress(&pqkv, g_qkv);
    cudaGetSymbolAddress(&pattn, g_attnout);
    cudaGetSymbolAddress(&pproj, g_projout);
    cudaGetSymbolAddress(&px1, g_x1);
    cudaGetSymbolAddress(&ph2in, g_h2in);
    cudaGetSymbolAddress(&ph2mid, g_h2mid);
    cudaGetSymbolAddress(&pwqkv, g_wqkv);
    cudaGetSymbolAddress(&pwproj, g_wproj);
    cudaGetSymbolAddress(&pwfc1, g_wfc1);
    cudaGetSymbolAddress(&pwfc2, g_wfc2);

    cudaFuncSetAttribute(gemm2<0>, cudaFuncAttributeMaxDynamicSharedMemorySize, GEMM_SMEM);
    cudaFuncSetAttribute(gemm2<1>, cudaFuncAttributeMaxDynamicSharedMemorySize, GEMM_SMEM);
    cudaFuncSetAttribute(gemm2<2>, cudaFuncAttributeMaxDynamicSharedMemorySize, GEMM_SMEM);
    cudaFuncSetAttribute(gemm2<3>, cudaFuncAttributeMaxDynamicSharedMemorySize, GEMM_SMEM);

    // 1-4: weight conversions
    f2bf_kernel<<<(3 * DIMC * DIMC + 255) / 256, 256>>>(qkvw, (__nv_bfloat16*)pwqkv, 3 * DIMC * DIMC);
    f2bf_kernel<<<(DIMC * DIMC + 255) / 256, 256>>>(projw, (__nv_bfloat16*)pwproj, DIMC * DIMC);
    f2bf_kernel<<<(HID * DIMC + 255) / 256, 256>>>(fc1w, (__nv_bfloat16*)pwfc1, HID * DIMC);
    f2bf_kernel<<<(DIMC * HID + 255) / 256, 256>>>(fc2w, (__nv_bfloat16*)pwfc2, DIMC * HID);

    // 5: LN1 + window partition
    ln1_window_kernel<<<TOKW / 8, 256>>>(x, n1w, n1b);

    // 6: QKV GEMM -> bf16 (target for ncu capture)
    gemm2<1><<<dim3(3, TOKW / BM), 256, GEMM_SMEM>>>(TOKW, 3 * DIMC, DIMC,
        (const __nv_bfloat16*)pA1, (const __nv_bfloat16*)pwqkv, qkvb,
        nullptr, (__nv_bfloat16*)pqkv, nullptr, nullptr);

    // 7: bias table precompute
    bias_pre_kernel<<<NHEAD * NWIN, 256>>>(btab);

    // 8: fused windowed attention (tensor core)
    attn_kernel<<<dim3(NHEAD, BWN), 288>>>();

    // 9: proj GEMM -> fp32 (window layout)
    gemm2<0><<<dim3(1, TOKW / BM), 256, GEMM_SMEM>>>(TOKW, DIMC, DIMC,
        (const __nv_bfloat16*)pattn, (const __nv_bfloat16*)pwproj, projb,
        (float*)pproj, nullptr, nullptr, nullptr);

    // 10: un-window + residual + LN2
    unwin_res_ln2_kernel<<<L_TOK / 8, 256>>>(x, n2w, n2b);

    // 11: fc1 (+ exact GELU) -> bf16
    gemm2<2><<<dim3(4, (L_TOK + BM - 1) / BM), 256, GEMM_SMEM>>>(L_TOK, HID, DIMC,
        (const __nv_bfloat16*)ph2in, (const __nv_bfloat16*)pwfc1, fc1b,
        nullptr, (__nv_bfloat16*)ph2mid, nullptr, nullptr);

    // 12: fc2 + residual -> d_out
    gemm2<3><<<dim3(1, (L_TOK + BM - 1) / BM), 256, GEMM_SMEM>>>(L_TOK, DIMC, HID,
        (const __nv_bfloat16*)ph2mid, (const __nv_bfloat16*)pwfc2, fc2b,
        nullptr, nullptr, (const float*)px1, out);
}

// round 6
// speedup vs baseline: 2.6943x; 1.3103x over previous
#include <cuda_runtime.h>
#include <cuda_bf16.h>
#include <math.h>
#include <stdint.h>

// ---------------- problem constants ----------------
#define L_TOK   131040          // 8*91*180
#define TOKW    138240          // 960 windows * 144 tokens
#define DIMC    192
#define HID     768
#define NHEAD   6
#define HDIM    32
#define NTOK    144             // tokens per window (2*6*12)
#define NWIN    64              // windows per lon-group (4*16)
#define NLON    15
#define BWN     960             // NLON*NWIN
#define BROWS   3312            // bias table rows: 4*36*23

// GEMM tiling
#define BM 128
#define BN 192
#define BK 32
#define GSTAGES 4
#define PADK 40
#define STAGE_ELEMS ((BM + BN) * PADK)   // 12800 elems, 25600 B
#define GEMM_SMEM (STAGE_ELEMS * 2 * GSTAGES)  // 102400 B

// attention smem layout
#define APAD 40                          // row stride in halves for q/k/v
#define MATH (NTOK * APAD)               // 5760 halves per matrix
#define MATB (MATH * 2)                  // 11520 bytes
#define STAGEB (3 * MATB)                // 34560 bytes per stage
#define PADB 146                         // bias row stride (halves)
#define BIASB (NTOK * PADB * 2)          // 42048 bytes
#define ATTN_SMEM (2 * STAGEB + BIASB + 2 * NTOK * 4)   // 112320

// ---------------- scratch buffers ----------------
__device__ __nv_bfloat16 g_A1[(size_t)TOKW * DIMC];
__device__ __nv_bfloat16 g_qkv[(size_t)TOKW * 3 * DIMC];
__device__ float         g_btabT[(size_t)NWIN * NHEAD * BROWS];   // [b2][bidx]
__device__ __nv_bfloat16 g_attnout[(size_t)TOKW * DIMC];
__device__ __nv_bfloat16 g_projout[(size_t)TOKW * DIMC];
__device__ float         g_x1[(size_t)L_TOK * DIMC];
__device__ __nv_bfloat16 g_h2in[(size_t)L_TOK * DIMC];
__device__ __nv_bfloat16 g_h2mid[(size_t)L_TOK * HID];
__device__ __nv_bfloat16 g_wqkv[3 * DIMC * DIMC];
__device__ __nv_bfloat16 g_wproj[DIMC * DIMC];
__device__ __nv_bfloat16 g_wfc1[HID * DIMC];
__device__ __nv_bfloat16 g_wfc2[DIMC * HID];

// ---------------- helpers ----------------
__device__ __forceinline__ void cp_async16(uint32_t saddr, const void* gptr, bool pred) {
    int sz = pred ? 16 : 0;
    asm volatile("cp.async.cg.shared.global [%0], [%1], 16, %2;\n"
                 :: "r"(saddr), "l"(gptr), "r"(sz));
}

__device__ __forceinline__ void ldsm4(uint32_t* r, uint32_t addr) {
    asm volatile("ldmatrix.sync.aligned.m8n8.x4.shared.b16 {%0,%1,%2,%3}, [%4];\n"
                 : "=r"(r[0]), "=r"(r[1]), "=r"(r[2]), "=r"(r[3]) : "r"(addr));
}

__device__ __forceinline__ void ldsm4t(uint32_t* r, uint32_t addr) {
    asm volatile("ldmatrix.sync.aligned.m8n8.x4.trans.shared.b16 {%0,%1,%2,%3}, [%4];\n"
                 : "=r"(r[0]), "=r"(r[1]), "=r"(r[2]), "=r"(r[3]) : "r"(addr));
}

__device__ __forceinline__ void mma16816(float* d, const uint32_t* a, const uint32_t* b) {
    asm volatile(
        "mma.sync.aligned.m16n8k16.row.col.f32.bf16.bf16.f32 "
        "{%0,%1,%2,%3}, {%4,%5,%6,%7}, {%8,%9}, {%0,%1,%2,%3};\n"
        : "+f"(d[0]), "+f"(d[1]), "+f"(d[2]), "+f"(d[3])
        : "r"(a[0]), "r"(a[1]), "r"(a[2]), "r"(a[3]), "r"(b[0]), "r"(b[1]));
}

__device__ __forceinline__ uint32_t packbf2(float lo, float hi) {
    __nv_bfloat162 p = __nv_bfloat162(__float2bfloat16(lo), __float2bfloat16(hi));
    return *reinterpret_cast<uint32_t*>(&p);
}

// ---------------- merged weight conversion ----------------
__global__ __launch_bounds__(256) void wconv_kernel(
    const float* __restrict__ s0, const float* __restrict__ s1,
    const float* __restrict__ s2, const float* __restrict__ s3) {
    int i = blockIdx.x * 256 + threadIdx.x;
    if (i < 110592)      g_wqkv[i]  = __float2bfloat16(s0[i]);
    else if (i < 147456) { int j = i - 110592;  g_wproj[j] = __float2bfloat16(s1[j]); }
    else if (i < 294912) { int j = i - 147456;  g_wfc1[j]  = __float2bfloat16(s2[j]); }
    else if (i < 442368) { int j = i - 294912;  g_wfc2[j]  = __float2bfloat16(s3[j]); }
}

// ---------------- bias table transpose: [bidx][b2] -> [b2][bidx] ----------------
__global__ __launch_bounds__(256) void btab_t_kernel(const float* __restrict__ btab) {
    int e = blockIdx.x * 256 + threadIdx.x;
    if (e < BROWS * NWIN * NHEAD) {
        int b2 = e / BROWS, bidx = e - b2 * BROWS;
        g_btabT[e] = btab[(size_t)bidx * (NWIN * NHEAD) + b2];
    }
}

// ---------------- LN1 + pad + roll + window partition (warp per token) ----------------
__global__ __launch_bounds__(256) void ln1_window_kernel(const float* __restrict__ x,
                                                          const float* __restrict__ w,
                                                          const float* __restrict__ b) {
    int t = blockIdx.x * 8 + (threadIdx.x >> 5);
    int lane = threadIdx.x & 31;
    int bw = t / NTOK, n = t - bw * NTOK;
    int li = bw >> 6, wdw = bw & 63;
    int wp_i = n / 72, wa_i = (n / 12) % 6, wo_i = n % 12;
    int pl_p  = (wdw >> 4) * 2 + wp_i;
    int lat_p = (wdw & 15) * 6 + wa_i;
    int lon_p = li * 12 + wo_i;
    int pl_s  = (pl_p + 1) & 7;
    int lat_s = (lat_p + 3) % 96;
    int lon_s = (lon_p + 6) % 180;
    int lat_o = lat_s - 2;
    bool valid = (lat_o >= 0) && (lat_o < 91);
    size_t src = valid ? ((size_t)(pl_s * 91 + lat_o) * 180 + lon_s) * DIMC : 0;
    float v[6]; float s = 0.f, s2 = 0.f;
    #pragma unroll
    for (int k = 0; k < 6; k++) {
        float vv = valid ? x[src + lane + 32 * k] : 0.f;
        v[k] = vv; s += vv; s2 += vv * vv;
    }
    #pragma unroll
    for (int o = 16; o > 0; o >>= 1) {
        s  += __shfl_xor_sync(0xffffffffu, s, o);
        s2 += __shfl_xor_sync(0xffffffffu, s2, o);
    }
    float mean = s * (1.f / 192.f);
    float var  = s2 * (1.f / 192.f) - mean * mean;
    float rstd = rsqrtf(var + 1e-5f);
    #pragma unroll
    for (int k = 0; k < 6; k++) {
        int c = lane + 32 * k;
        float h = valid ? (v[k] - mean) * rstd * w[c] + b[c] : 0.f;
        g_A1[(size_t)t * DIMC + c] = __float2bfloat16(h);
    }
}

// ---------------- bf16 GEMM: 256 thr, warp tile 64x48, 4-stage cp.async ------------
// MODE 1: bf16 out + bias   MODE 2: gelu(acc+bias) -> bf16   MODE 3: Out = X1 + acc + bias (fp32)
template <int MODE>
__global__ __launch_bounds__(256, 1) void gemm2(
    int M, int N, int K,
    const __nv_bfloat16* __restrict__ A,
    const __nv_bfloat16* __restrict__ Bw,
    const float* __restrict__ bias,
    __nv_bfloat16* __restrict__ Cb,
    const float* __restrict__ X1,
    float* __restrict__ Out) {
    extern __shared__ __align__(16) unsigned char smraw[];
    uint32_t smem_u32 = (uint32_t)__cvta_generic_to_shared(smraw);

    const int tid = threadIdx.x;
    const int lane = tid & 31, warp = tid >> 5;
    const int m0 = blockIdx.y * BM;
    const int n0 = blockIdx.x * BN;
    const int wm = (warp >> 2) * 64;
    const int wn = (warp & 3) * 48;
    const int KT = K >> 5;

    float acc[4][6][4];
    #pragma unroll
    for (int a = 0; a < 4; a++)
        #pragma unroll
        for (int b2 = 0; b2 < 6; b2++)
            #pragma unroll
            for (int c = 0; c < 4; c++) acc[a][b2][c] = 0.f;

    auto load_stage = [&](int stage, int kt) {
        const int kb = kt << 5;
        uint32_t sbase = smem_u32 + stage * (STAGE_ELEMS * 2);
        #pragma unroll
        for (int it = 0; it < 2; it++) {
            int q = tid + it * 256;
            int row = q >> 2, col = (q & 3) << 3;
            int gr = m0 + row;
            bool p = gr < M;
            const __nv_bfloat16* gp = A + (size_t)(p ? gr : 0) * K + kb + col;
            cp_async16(sbase + (uint32_t)(row * PADK + col) * 2, gp, p);
        }
        uint32_t bbase = sbase + BM * PADK * 2;
        #pragma unroll
        for (int it = 0; it < 3; it++) {
            int q = tid + it * 256;
            int row = q >> 2, col = (q & 3) << 3;
            const __nv_bfloat16* gp = Bw + (size_t)(n0 + row) * K + kb + col;
            cp_async16(bbase + (uint32_t)(row * PADK + col) * 2, gp, true);
        }
    };

    #pragma unroll
    for (int s = 0; s < GSTAGES - 1; s++) {
        load_stage(s, s);
        asm volatile("cp.async.commit_group;\n");
    }

    for (int kt = 0; kt < KT; kt++) {
        asm volatile("cp.async.wait_group %0;\n" :: "n"(GSTAGES - 2));
        __syncthreads();
        int kn = kt + GSTAGES - 1;
        if (kn < KT) load_stage(kn % GSTAGES, kn);
        asm volatile("cp.async.commit_group;\n");

        uint32_t sbase = smem_u32 + (kt % GSTAGES) * (STAGE_ELEMS * 2);
        #pragma unroll
        for (int kk = 0; kk < 32; kk += 16) {
            uint32_t af[4][4], bfr[3][4];
            #pragma unroll
            for (int mi = 0; mi < 4; mi++) {
                uint32_t addr = sbase +
                    (uint32_t)(((wm + mi * 16 + (lane & 15)) * PADK) + kk + ((lane & 16) >> 1)) * 2;
                ldsm4(af[mi], addr);
            }
            #pragma unroll
            for (int nb = 0; nb < 3; nb++) {
                int nr = wn + nb * 16 + (lane & 7) + ((lane & 16) >> 1);
                uint32_t addr = sbase + BM * PADK * 2 +
                    (uint32_t)(nr * PADK + kk + (lane & 8)) * 2;
                ldsm4(bfr[nb], addr);
            }
            #pragma unroll
            for (int mi = 0; mi < 4; mi++)
                #pragma unroll
                for (int ni = 0; ni < 6; ni++)
                    mma16816(acc[mi][ni], af[mi], &bfr[ni >> 1][(ni & 1) * 2]);
        }
    }

    // epilogue
    const int g = lane >> 2, c4 = lane & 3;
    #pragma unroll
    for (int mi = 0; mi < 4; mi++) {
        #pragma unroll
        for (int ni = 0; ni < 6; ni++) {
            int row0 = m0 + wm + mi * 16 + g;
            int col0 = n0 + wn + ni * 8 + 2 * c4;
            float2 bv = *(const float2*)(bias + col0);
            #pragma unroll
            for (int rr = 0; rr < 2; rr++) {
                int row = row0 + rr * 8;
                if (row >= M) continue;
                float v0 = acc[mi][ni][rr * 2 + 0] + bv.x;
                float v1 = acc[mi][ni][rr * 2 + 1] + bv.y;
                size_t off = (size_t)row * N + col0;
                if (MODE == 1) {
                    *(__nv_bfloat162*)(Cb + off) =
                        __nv_bfloat162(__float2bfloat16(v0), __float2bfloat16(v1));
                } else if (MODE == 2) {
                    float g0 = 0.5f * v0 * (1.0f + erff(v0 * 0.70710678118654752f));
                    float g1 = 0.5f * v1 * (1.0f + erff(v1 * 0.70710678118654752f));
                    *(__nv_bfloat162*)(Cb + off) =
                        __nv_bfloat162(__float2bfloat16(g0), __float2bfloat16(g1));
                } else {
                    float2 xv = *(const float2*)(X1 + off);
                    *(float2*)(Out + off) = make_float2(xv.x + v0, xv.y + v1);
                }
            }
        }
    }
}

// ---------------- tensor-core windowed attention, bias reused across 15 lon-groups ----------
// block = (head, wdw); 9 warps; loop li=0..14 with double-buffered cp.async qkv staging.
__global__ __launch_bounds__(288, 1) void attn_kernel() {
    const int head = blockIdx.x;
    const int wdw = blockIdx.y;
    const int tid = threadIdx.x;
    const int lane = tid & 31;
    const int warp = tid >> 5;

    extern __shared__ __align__(16) unsigned char smraw[];
    __nv_bfloat16* sbias = (__nv_bfloat16*)(smraw + 2 * STAGEB);
    int* sid0  = (int*)(smraw + 2 * STAGEB + BIASB);
    int* sid14 = sid0 + NTOK;
    uint32_t squ = (uint32_t)__cvta_generic_to_shared(smraw);

    auto load_st = [&](int st, int li) {
        int bw = li * NWIN + wdw;
        const __nv_bfloat16* gb = g_qkv + (size_t)bw * NTOK * (3 * DIMC) + head * HDIM;
        uint32_t sb = squ + st * STAGEB;
        #pragma unroll
        for (int s = 0; s < 6; s++) {
            int c = tid + s * 288;                 // 0..1727
            int mat = c / 576, rem = c - mat * 576, j = rem >> 2, q16 = rem & 3;
            const void* gp = gb + (size_t)j * (3 * DIMC) + mat * DIMC + q16 * 8;
            cp_async16(sb + (uint32_t)(mat * MATB + j * (APAD * 2) + q16 * 16), gp, true);
        }
    };

    // prefetch li=0 while gathering bias
    load_st(0, 0);
    asm volatile("cp.async.commit_group;\n");

    if (tid < NTOK) {
        int n = tid;
        int wp_i = n / 72, wa_i = (n / 12) % 6, wo_i = n % 12;
        int pl_p  = (wdw >> 4) * 2 + wp_i;
        int lat_p = (wdw & 15) * 6 + wa_i;
        int rpl  = pl_p  < 6  ? 0 : (pl_p  < 7  ? 1 : 2);
        int rlat = lat_p < 90 ? 0 : (lat_p < 93 ? 1 : 2);
        int base = (rpl * 3 + rlat) * 3;
        sid0[n]  = base;
        sid14[n] = base + ((168 + wo_i) >= 174 ? 1 : 0);
    }
    {
        const float* bt = g_btabT + (size_t)(wdw * NHEAD + head) * BROWS;
        for (int e = tid; e < NTOK * NTOK; e += 288) {
            int i = e / NTOK, j = e - i * NTOK;
            int zi = i / 72, hi = (i / 12) % 6, wi = i % 12;
            int zj = j / 72, hj = (j / 12) % 6, wj = j % 12;
            int bidx = (zi + 2 * zj) * 828 + (hi + 6 * hj) * 23 + (wi - wj + 11);
            sbias[i * PADB + j] = __float2bfloat16(bt[bidx]);
        }
    }

    const int qrow0 = warp * 16;
    const int g = lane >> 2, c4 = lane & 3;
    const int row0 = qrow0 + g, row1 = row0 + 8;
    const float qscale = 0.17677669529663687f;   // 1/sqrt(32)

    for (int li = 0; li < NLON; li++) {
        if (li + 1 < NLON) {
            load_st((li + 1) & 1, li + 1);
            asm volatile("cp.async.commit_group;\n");
            asm volatile("cp.async.wait_group 1;\n");
        } else {
            asm volatile("cp.async.wait_group 0;\n");
        }
        __syncthreads();

        uint32_t sq_b = squ + (li & 1) * STAGEB;
        uint32_t sk_b = sq_b + MATB;
        uint32_t sv_b = sk_b + MATB;
        const int* sregp = (li == 14) ? sid14 : sid0;

        // Q fragments
        uint32_t aq[2][4];
        #pragma unroll
        for (int kkidx = 0; kkidx < 2; kkidx++) {
            uint32_t addr = sq_b + (uint32_t)((qrow0 + (lane & 15)) * (APAD * 2)
                                              + kkidx * 32 + (lane & 16));
            ldsm4(aq[kkidx], addr);
        }

        // S = Q K^T
        float sacc[18][4];
        #pragma unroll
        for (int t = 0; t < 18; t++)
            #pragma unroll
            for (int c = 0; c < 4; c++) sacc[t][c] = 0.f;

        #pragma unroll
        for (int nt = 0; nt < 9; nt++) {
            #pragma unroll
            for (int kkidx = 0; kkidx < 2; kkidx++) {
                uint32_t bk[4];
                uint32_t addr = sk_b +
                    (uint32_t)((nt * 16 + (lane & 7) + ((lane & 16) >> 1)) * (APAD * 2)
                               + kkidx * 32 + (lane & 8) * 2);
                ldsm4(bk, addr);
                mma16816(sacc[2 * nt],     aq[kkidx], &bk[0]);
                mma16816(sacc[2 * nt + 1], aq[kkidx], &bk[2]);
            }
        }

        // scale + bias + mask
        const int rg0 = sregp[row0], rg1 = sregp[row1];
        #pragma unroll
        for (int t = 0; t < 18; t++) {
            int col = t * 8 + 2 * c4;
            float2 b0 = __bfloat1622float2(*(const __nv_bfloat162*)(sbias + row0 * PADB + col));
            float2 b1 = __bfloat1622float2(*(const __nv_bfloat162*)(sbias + row1 * PADB + col));
            int rc0 = sregp[col], rc1 = sregp[col + 1];
            sacc[t][0] = fmaf(sacc[t][0], qscale, b0.x + (rc0 != rg0 ? -100.f : 0.f));
            sacc[t][1] = fmaf(sacc[t][1], qscale, b0.y + (rc1 != rg0 ? -100.f : 0.f));
            sacc[t][2] = fmaf(sacc[t][2], qscale, b1.x + (rc0 != rg1 ? -100.f : 0.f));
            sacc[t][3] = fmaf(sacc[t][3], qscale, b1.y + (rc1 != rg1 ? -100.f : 0.f));
        }

        // softmax over rows row0, row1 (quad reduce)
        float mx0 = -1e30f, mx1 = -1e30f;
        #pragma unroll
        for (int t = 0; t < 18; t++) {
            mx0 = fmaxf(mx0, fmaxf(sacc[t][0], sacc[t][1]));
            mx1 = fmaxf(mx1, fmaxf(sacc[t][2], sacc[t][3]));
        }
        #pragma unroll
        for (int o = 1; o <= 2; o <<= 1) {
            mx0 = fmaxf(mx0, __shfl_xor_sync(0xffffffffu, mx0, o));
            mx1 = fmaxf(mx1, __shfl_xor_sync(0xffffffffu, mx1, o));
        }
        float sum0 = 0.f, sum1 = 0.f;
        #pragma unroll
        for (int t = 0; t < 18; t++) {
            sacc[t][0] = __expf(sacc[t][0] - mx0);
            sacc[t][1] = __expf(sacc[t][1] - mx0);
            sacc[t][2] = __expf(sacc[t][2] - mx1);
            sacc[t][3] = __expf(sacc[t][3] - mx1);
            sum0 += sacc[t][0] + sacc[t][1];
            sum1 += sacc[t][2] + sacc[t][3];
        }
        #pragma unroll
        for (int o = 1; o <= 2; o <<= 1) {
            sum0 += __shfl_xor_sync(0xffffffffu, sum0, o);
            sum1 += __shfl_xor_sync(0xffffffffu, sum1, o);
        }
        float inv0 = 1.f / sum0, inv1 = 1.f / sum1;

        // pack P as A fragments
        uint32_t ap[9][4];
        #pragma unroll
        for (int kt = 0; kt < 9; kt++) {
            ap[kt][0] = packbf2(sacc[2 * kt][0],     sacc[2 * kt][1]);
            ap[kt][1] = packbf2(sacc[2 * kt][2],     sacc[2 * kt][3]);
            ap[kt][2] = packbf2(sacc[2 * kt + 1][0], sacc[2 * kt + 1][1]);
            ap[kt][3] = packbf2(sacc[2 * kt + 1][2], sacc[2 * kt + 1][3]);
        }

        // O = P V  (V row-layout [j][d], B frags via ldmatrix.trans)
        float oacc[4][4];
        #pragma unroll
        for (int t = 0; t < 4; t++)
            #pragma unroll
            for (int c = 0; c < 4; c++) oacc[t][c] = 0.f;

        #pragma unroll
        for (int kt = 0; kt < 9; kt++) {
            #pragma unroll
            for (int dh = 0; dh < 2; dh++) {
                uint32_t bv[4];
                uint32_t addr = sv_b +
                    (uint32_t)((kt * 16 + (lane & 15)) * (APAD * 2) + dh * 32 + (lane & 16));
                ldsm4t(bv, addr);
                mma16816(oacc[2 * dh],     ap[kt], &bv[0]);
                mma16816(oacc[2 * dh + 1], ap[kt], &bv[2]);
            }
        }

        // write out
        int bw = li * NWIN + wdw;
        #pragma unroll
        for (int dt = 0; dt < 4; dt++) {
            int col = head * HDIM + dt * 8 + 2 * c4;
            size_t t0 = (size_t)(bw * NTOK + row0) * DIMC + col;
            size_t t1 = (size_t)(bw * NTOK + row1) * DIMC + col;
            *(__nv_bfloat162*)(g_attnout + t0) =
                __nv_bfloat162(__float2bfloat16(oacc[dt][0] * inv0), __float2bfloat16(oacc[dt][1] * inv0));
            *(__nv_bfloat162*)(g_attnout + t1) =
                __nv_bfloat162(__float2bfloat16(oacc[dt][2] * inv1), __float2bfloat16(oacc[dt][3] * inv1));
        }
        __syncthreads();
    }
}

// ---------------- un-window + residual + LN2 (warp per token) ----------------
__global__ __launch_bounds__(256) void unwin_res_ln2_kernel(const float* __restrict__ x,
                                                             const float* __restrict__ w,
                                                             const float* __restrict__ b) {
    int t = blockIdx.x * 8 + (threadIdx.x >> 5);
    int lane = threadIdx.x & 31;
    int pl = t / (91 * 180);
    int rem = t - pl * (91 * 180);
    int lat = rem / 180, lon = rem % 180;
    int pl_p  = (pl + 7) & 7;
    int lat_p = (lat + 95) % 96;
    int lon_p = (lon + 174) % 180;
    int plg = pl_p >> 1, wp_i = pl_p & 1;
    int latg = lat_p / 6, wa_i = lat_p % 6;
    int li = lon_p / 12, wo_i = lon_p % 12;
    int wdw = plg * 16 + latg;
    int n = (wp_i * 6 + wa_i) * 12 + wo_i;
    size_t slot = ((size_t)((li * NWIN + wdw) * NTOK + n)) * DIMC;
    size_t base = (size_t)t * DIMC;
    float v[6]; float s = 0.f, s2 = 0.f;
    #pragma unroll
    for (int k = 0; k < 6; k++) {
        int c = lane + 32 * k;
        float vv = x[base + c] + __bfloat162float(g_projout[slot + c]);
        v[k] = vv; s += vv; s2 += vv * vv;
        g_x1[base + c] = vv;
    }
    #pragma unroll
    for (int o = 16; o > 0; o >>= 1) {
        s  += __shfl_xor_sync(0xffffffffu, s, o);
        s2 += __shfl_xor_sync(0xffffffffu, s2, o);
    }
    float mean = s * (1.f / 192.f);
    float var  = s2 * (1.f / 192.f) - mean * mean;
    float rstd = rsqrtf(var + 1e-5f);
    #pragma unroll
    for (int k = 0; k < 6; k++) {
        int c = lane + 32 * k;
        float h = (v[k] - mean) * rstd * w[c] + b[c];
        g_h2in[base + c] = __float2bfloat16(h);
    }
}

// ---------------- launch ----------------
extern "C" void kernel_launch(void* const* d_in, const int* in_sizes, int n_in,
                              void* d_out, int out_size) {
    const float* x     = (const float*)d_in[0];
    const float* n1w   = (const float*)d_in[1];
    const float* n1b   = (const float*)d_in[2];
    const float* qkvw  = (const float*)d_in[3];
    const float* qkvb  = (const float*)d_in[4];
    const float* btab  = (const float*)d_in[5];
    const float* projw = (const float*)d_in[6];
    const float* projb = (const float*)d_in[7];
    const float* n2w   = (const float*)d_in[8];
    const float* n2b   = (const float*)d_in[9];
    const float* fc1w  = (const float*)d_in[10];
    const float* fc1b  = (const float*)d_in[11];
    const float* fc2w  = (const float*)d_in[12];
    const float* fc2b  = (const float*)d_in[13];
    float* out = (float*)d_out;

    void *pA1, *pqkv, *pattn, *pproj, *px1, *ph2in, *ph2mid;
    void *pwqkv, *pwproj, *pwfc1, *pwfc2;
    cudaGetSymbolAddress(&pA1, g_A1);
    cudaGetSymbolAddress(&pqkv, g_qkv);
    cudaGetSymbolAddress(&pattn, g_attnout);
    cudaGetSymbolAddress(&pproj, g_projout);
    cudaGetSymbolAddress(&px1, g_x1);
    cudaGetSymbolAddress(&ph2in, g_h2in);
    cudaGetSymbolAddress(&ph2mid, g_h2mid);
    cudaGetSymbolAddress(&pwqkv, g_wqkv);
    cudaGetSymbolAddress(&pwproj, g_wproj);
    cudaGetSymbolAddress(&pwfc1, g_wfc1);
    cudaGetSymbolAddress(&pwfc2, g_wfc2);

    cudaFuncSetAttribute(gemm2<1>, cudaFuncAttributeMaxDynamicSharedMemorySize, GEMM_SMEM);
    cudaFuncSetAttribute(gemm2<2>, cudaFuncAttributeMaxDynamicSharedMemorySize, GEMM_SMEM);
    cudaFuncSetAttribute(gemm2<3>, cudaFuncAttributeMaxDynamicSharedMemorySize, GEMM_SMEM);
    cudaFuncSetAttribute(attn_kernel, cudaFuncAttributeMaxDynamicSharedMemorySize, ATTN_SMEM);

    // 1: merged weight conversions
    wconv_kernel<<<1728, 256>>>(qkvw, projw, fc1w, fc2w);

    // 2: bias table transpose
    btab_t_kernel<<<(BROWS * NWIN * NHEAD + 255) / 256, 256>>>(btab);

    // 3: LN1 + window partition
    ln1_window_kernel<<<TOKW / 8, 256>>>(x, n1w, n1b);

    // 4: QKV GEMM -> bf16
    gemm2<1><<<dim3(3, TOKW / BM), 256, GEMM_SMEM>>>(TOKW, 3 * DIMC, DIMC,
        (const __nv_bfloat16*)pA1, (const __nv_bfloat16*)pwqkv, qkvb,
        (__nv_bfloat16*)pqkv, nullptr, nullptr);

    // 5: fused windowed attention (bias reused across lon groups)
    attn_kernel<<<dim3(NHEAD, NWIN), 288, ATTN_SMEM>>>();

    // 6: proj GEMM -> bf16 (window layout)
    gemm2<1><<<dim3(1, TOKW / BM), 256, GEMM_SMEM>>>(TOKW, DIMC, DIMC,
        (const __nv_bfloat16*)pattn, (const __nv_bfloat16*)pwproj, projb,
        (__nv_bfloat16*)pproj, nullptr, nullptr);

    // 7: un-window + residual + LN2
    unwin_res_ln2_kernel<<<L_TOK / 8, 256>>>(x, n2w, n2b);

    // 8: fc1 (+ exact GELU) -> bf16
    gemm2<2><<<dim3(4, (L_TOK + BM - 1) / BM), 256, GEMM_SMEM>>>(L_TOK, HID, DIMC,
        (const __nv_bfloat16*)ph2in, (const __nv_bfloat16*)pwfc1, fc1b,
        (__nv_bfloat16*)ph2mid, nullptr, nullptr);

    // 9: fc2 + residual -> d_out
    gemm2<3><<<dim3(1, (L_TOK + BM - 1) / BM), 256, GEMM_SMEM>>>(L_TOK, DIMC, HID,
        (const __nv_bfloat16*)ph2mid, (const __nv_bfloat16*)pwfc2, fc2b,
        nullptr, (const float*)px1, out);
}

// round 7
// speedup vs baseline: 2.9235x; 1.0851x over previous
#include <cuda_runtime.h>
#include <cuda_bf16.h>
#include <math.h>
#include <stdint.h>

// ---------------- problem constants ----------------
#define L_TOK   131040          // 8*91*180
#define TOKW    138240          // 960 windows * 144 tokens
#define DIMC    192
#define HID     768
#define NHEAD   6
#define HDIM    32
#define NTOK    144             // tokens per window (2*6*12)
#define NWIN    64              // windows per lon-group (4*16)
#define NLON    15
#define BWN     960             // NLON*NWIN
#define BROWS   3312            // bias table rows: 4*36*23

// GEMM tiling (2 CTAs / SM)
#define BM 64
#define BN 192
#define BK 32
#define GSTAGES 4
#define PADK 40
#define STAGE_ELEMS ((BM + BN) * PADK)   // 10240 elems, 20480 B
#define GEMM_SMEM (STAGE_ELEMS * 2 * GSTAGES)  // 81920 B

// attention smem layout
#define APAD 40                          // row stride in halves for q/k/v
#define MATH (NTOK * APAD)               // 5760 halves per matrix
#define MATB (MATH * 2)                  // 11520 bytes
#define STAGEB (3 * MATB)                // 34560 bytes per stage
#define PADB 146                         // bias row stride (halves)
#define BIASB (NTOK * PADB * 2)          // 42048 bytes
#define ATTN_SMEM (2 * STAGEB + BIASB + 2 * NTOK * 4)   // 112320

// ---------------- scratch buffers ----------------
__device__ __nv_bfloat16 g_A1[(size_t)TOKW * DIMC];
__device__ __nv_bfloat16 g_qkv[(size_t)TOKW * 3 * DIMC];
__device__ float         g_btabT[(size_t)NWIN * NHEAD * BROWS];   // [b2][bidx]
__device__ __nv_bfloat16 g_attnout[(size_t)TOKW * DIMC];
__device__ __nv_bfloat16 g_projout[(size_t)TOKW * DIMC];
__device__ float         g_x1[(size_t)L_TOK * DIMC];
__device__ __nv_bfloat16 g_h2in[(size_t)L_TOK * DIMC];
__device__ __nv_bfloat16 g_h2mid[(size_t)L_TOK * HID];
__device__ __nv_bfloat16 g_wqkv[3 * DIMC * DIMC];
__device__ __nv_bfloat16 g_wproj[DIMC * DIMC];
__device__ __nv_bfloat16 g_wfc1[HID * DIMC];
__device__ __nv_bfloat16 g_wfc2[DIMC * HID];

// ---------------- helpers ----------------
__device__ __forceinline__ void cp_async16(uint32_t saddr, const void* gptr, bool pred) {
    int sz = pred ? 16 : 0;
    asm volatile("cp.async.cg.shared.global [%0], [%1], 16, %2;\n"
                 :: "r"(saddr), "l"(gptr), "r"(sz));
}

__device__ __forceinline__ void ldsm4(uint32_t* r, uint32_t addr) {
    asm volatile("ldmatrix.sync.aligned.m8n8.x4.shared.b16 {%0,%1,%2,%3}, [%4];\n"
                 : "=r"(r[0]), "=r"(r[1]), "=r"(r[2]), "=r"(r[3]) : "r"(addr));
}

__device__ __forceinline__ void ldsm4t(uint32_t* r, uint32_t addr) {
    asm volatile("ldmatrix.sync.aligned.m8n8.x4.trans.shared.b16 {%0,%1,%2,%3}, [%4];\n"
                 : "=r"(r[0]), "=r"(r[1]), "=r"(r[2]), "=r"(r[3]) : "r"(addr));
}

__device__ __forceinline__ void mma16816(float* d, const uint32_t* a, const uint32_t* b) {
    asm volatile(
        "mma.sync.aligned.m16n8k16.row.col.f32.bf16.bf16.f32 "
        "{%0,%1,%2,%3}, {%4,%5,%6,%7}, {%8,%9}, {%0,%1,%2,%3};\n"
        : "+f"(d[0]), "+f"(d[1]), "+f"(d[2]), "+f"(d[3])
        : "r"(a[0]), "r"(a[1]), "r"(a[2]), "r"(a[3]), "r"(b[0]), "r"(b[1]));
}

__device__ __forceinline__ uint32_t packbf2(float lo, float hi) {
    __nv_bfloat162 p = __nv_bfloat162(__float2bfloat16(lo), __float2bfloat16(hi));
    return *reinterpret_cast<uint32_t*>(&p);
}

// ---------------- merged weight conversion ----------------
__global__ __launch_bounds__(256) void wconv_kernel(
    const float* __restrict__ s0, const float* __restrict__ s1,
    const float* __restrict__ s2, const float* __restrict__ s3) {
    int i = blockIdx.x * 256 + threadIdx.x;
    if (i < 110592)      g_wqkv[i]  = __float2bfloat16(s0[i]);
    else if (i < 147456) { int j = i - 110592;  g_wproj[j] = __float2bfloat16(s1[j]); }
    else if (i < 294912) { int j = i - 147456;  g_wfc1[j]  = __float2bfloat16(s2[j]); }
    else if (i < 442368) { int j = i - 294912;  g_wfc2[j]  = __float2bfloat16(s3[j]); }
}

// ---------------- bias table transpose: [bidx][b2] -> [b2][bidx] ----------------
__global__ __launch_bounds__(256) void btab_t_kernel(const float* __restrict__ btab) {
    int e = blockIdx.x * 256 + threadIdx.x;
    if (e < BROWS * NWIN * NHEAD) {
        int b2 = e / BROWS, bidx = e - b2 * BROWS;
        g_btabT[e] = btab[(size_t)bidx * (NWIN * NHEAD) + b2];
    }
}

// ---------------- LN1 + pad + roll + window partition (warp per token) ----------------
__global__ __launch_bounds__(256) void ln1_window_kernel(const float* __restrict__ x,
                                                          const float* __restrict__ w,
                                                          const float* __restrict__ b) {
    int t = blockIdx.x * 8 + (threadIdx.x >> 5);
    int lane = threadIdx.x & 31;
    int bw = t / NTOK, n = t - bw * NTOK;
    int li = bw >> 6, wdw = bw & 63;
    int wp_i = n / 72, wa_i = (n / 12) % 6, wo_i = n % 12;
    int pl_p  = (wdw >> 4) * 2 + wp_i;
    int lat_p = (wdw & 15) * 6 + wa_i;
    int lon_p = li * 12 + wo_i;
    int pl_s  = (pl_p + 1) & 7;
    int lat_s = (lat_p + 3) % 96;
    int lon_s = (lon_p + 6) % 180;
    int lat_o = lat_s - 2;
    bool valid = (lat_o >= 0) && (lat_o < 91);
    size_t src = valid ? ((size_t)(pl_s * 91 + lat_o) * 180 + lon_s) * DIMC : 0;
    float v[6]; float s = 0.f, s2 = 0.f;
    #pragma unroll
    for (int k = 0; k < 6; k++) {
        float vv = valid ? x[src + lane + 32 * k] : 0.f;
        v[k] = vv; s += vv; s2 += vv * vv;
    }
    #pragma unroll
    for (int o = 16; o > 0; o >>= 1) {
        s  += __shfl_xor_sync(0xffffffffu, s, o);
        s2 += __shfl_xor_sync(0xffffffffu, s2, o);
    }
    float mean = s * (1.f / 192.f);
    float var  = s2 * (1.f / 192.f) - mean * mean;
    float rstd = rsqrtf(var + 1e-5f);
    #pragma unroll
    for (int k = 0; k < 6; k++) {
        int c = lane + 32 * k;
        float h = valid ? (v[k] - mean) * rstd * w[c] + b[c] : 0.f;
        g_A1[(size_t)t * DIMC + c] = __float2bfloat16(h);
    }
}

// ---------------- bf16 GEMM: BM=64, 2 CTAs/SM, warp tile 32x48, 4-stage cp.async ----------
// MODE 1: bf16 out + bias   MODE 2: gelu(acc+bias) -> bf16   MODE 3: Out = X1 + acc + bias (fp32)
template <int MODE>
__global__ __launch_bounds__(256, 2) void gemm2(
    int M, int N, int K,
    const __nv_bfloat16* __restrict__ A,
    const __nv_bfloat16* __restrict__ Bw,
    const float* __restrict__ bias,
    __nv_bfloat16* __restrict__ Cb,
    const float* __restrict__ X1,
    float* __restrict__ Out) {
    extern __shared__ __align__(16) unsigned char smraw[];
    uint32_t smem_u32 = (uint32_t)__cvta_generic_to_shared(smraw);

    const int tid = threadIdx.x;
    const int lane = tid & 31, warp = tid >> 5;
    const int m0 = blockIdx.y * BM;
    const int n0 = blockIdx.x * BN;
    const int wm = (warp >> 2) * 32;   // 2 warp rows * 32
    const int wn = (warp & 3) * 48;    // 4 warp cols * 48
    const int KT = K >> 5;

    float acc[2][6][4];
    #pragma unroll
    for (int a = 0; a < 2; a++)
        #pragma unroll
        for (int b2 = 0; b2 < 6; b2++)
            #pragma unroll
            for (int c = 0; c < 4; c++) acc[a][b2][c] = 0.f;

    auto load_stage = [&](int stage, int kt) {
        const int kb = kt << 5;
        uint32_t sbase = smem_u32 + stage * (STAGE_ELEMS * 2);
        {   // A: 64 rows * 4 uint4 = 256
            int row = tid >> 2, col = (tid & 3) << 3;
            int gr = m0 + row;
            bool p = gr < M;
            const __nv_bfloat16* gp = A + (size_t)(p ? gr : 0) * K + kb + col;
            cp_async16(sbase + (uint32_t)(row * PADK + col) * 2, gp, p);
        }
        uint32_t bbase = sbase + BM * PADK * 2;
        #pragma unroll
        for (int it = 0; it < 3; it++) {   // B: 768 uint4
            int q = tid + it * 256;
            int row = q >> 2, col = (q & 3) << 3;
            const __nv_bfloat16* gp = Bw + (size_t)(n0 + row) * K + kb + col;
            cp_async16(bbase + (uint32_t)(row * PADK + col) * 2, gp, true);
        }
    };

    #pragma unroll
    for (int s = 0; s < GSTAGES - 1; s++) {
        load_stage(s, s);
        asm volatile("cp.async.commit_group;\n");
    }

    for (int kt = 0; kt < KT; kt++) {
        asm volatile("cp.async.wait_group %0;\n" :: "n"(GSTAGES - 2));
        __syncthreads();
        int kn = kt + GSTAGES - 1;
        if (kn < KT) load_stage(kn % GSTAGES, kn);
        asm volatile("cp.async.commit_group;\n");

        uint32_t sbase = smem_u32 + (kt % GSTAGES) * (STAGE_ELEMS * 2);
        #pragma unroll
        for (int kk = 0; kk < 32; kk += 16) {
            uint32_t af[2][4], bfr[3][4];
            #pragma unroll
            for (int mi = 0; mi < 2; mi++) {
                uint32_t addr = sbase +
                    (uint32_t)(((wm + mi * 16 + (lane & 15)) * PADK) + kk + ((lane & 16) >> 1)) * 2;
                ldsm4(af[mi], addr);
            }
            #pragma unroll
            for (int nb = 0; nb < 3; nb++) {
                int nr = wn + nb * 16 + (lane & 7) + ((lane & 16) >> 1);
                uint32_t addr = sbase + BM * PADK * 2 +
                    (uint32_t)(nr * PADK + kk + (lane & 8)) * 2;
                ldsm4(bfr[nb], addr);
            }
            #pragma unroll
            for (int mi = 0; mi < 2; mi++)
                #pragma unroll
                for (int ni = 0; ni < 6; ni++)
                    mma16816(acc[mi][ni], af[mi], &bfr[ni >> 1][(ni & 1) * 2]);
        }
    }

    // epilogue
    const int g = lane >> 2, c4 = lane & 3;
    #pragma unroll
    for (int mi = 0; mi < 2; mi++) {
        #pragma unroll
        for (int ni = 0; ni < 6; ni++) {
            int row0 = m0 + wm + mi * 16 + g;
            int col0 = n0 + wn + ni * 8 + 2 * c4;
            float2 bv = *(const float2*)(bias + col0);
            #pragma unroll
            for (int rr = 0; rr < 2; rr++) {
                int row = row0 + rr * 8;
                if (row >= M) continue;
                float v0 = acc[mi][ni][rr * 2 + 0] + bv.x;
                float v1 = acc[mi][ni][rr * 2 + 1] + bv.y;
                size_t off = (size_t)row * N + col0;
                if (MODE == 1) {
                    *(__nv_bfloat162*)(Cb + off) =
                        __nv_bfloat162(__float2bfloat16(v0), __float2bfloat16(v1));
                } else if (MODE == 2) {
                    float g0 = 0.5f * v0 * (1.0f + erff(v0 * 0.70710678118654752f));
                    float g1 = 0.5f * v1 * (1.0f + erff(v1 * 0.70710678118654752f));
                    *(__nv_bfloat162*)(Cb + off) =
                        __nv_bfloat162(__float2bfloat16(g0), __float2bfloat16(g1));
                } else {
                    float2 xv = *(const float2*)(X1 + off);
                    *(float2*)(Out + off) = make_float2(xv.x + v0, xv.y + v1);
                }
            }
        }
    }
}

// ---------------- tensor-core windowed attention, bias reused across 15 lon-groups ----------
__global__ __launch_bounds__(288, 1) void attn_kernel() {
    const int head = blockIdx.x;
    const int wdw = blockIdx.y;
    const int tid = threadIdx.x;
    const int lane = tid & 31;
    const int warp = tid >> 5;

    extern __shared__ __align__(16) unsigned char smraw[];
    __nv_bfloat16* sbias = (__nv_bfloat16*)(smraw + 2 * STAGEB);
    int* sid0  = (int*)(smraw + 2 * STAGEB + BIASB);
    int* sid14 = sid0 + NTOK;
    uint32_t squ = (uint32_t)__cvta_generic_to_shared(smraw);

    auto load_st = [&](int st, int li) {
        int bw = li * NWIN + wdw;
        const __nv_bfloat16* gb = g_qkv + (size_t)bw * NTOK * (3 * DIMC) + head * HDIM;
        uint32_t sb = squ + st * STAGEB;
        #pragma unroll
        for (int s = 0; s < 6; s++) {
            int c = tid + s * 288;
            int mat = c / 576, rem = c - mat * 576, j = rem >> 2, q16 = rem & 3;
            const void* gp = gb + (size_t)j * (3 * DIMC) + mat * DIMC + q16 * 8;
            cp_async16(sb + (uint32_t)(mat * MATB + j * (APAD * 2) + q16 * 16), gp, true);
        }
    };

    load_st(0, 0);
    asm volatile("cp.async.commit_group;\n");

    if (tid < NTOK) {
        int n = tid;
        int wp_i = n / 72, wa_i = (n / 12) % 6, wo_i = n % 12;
        int pl_p  = (wdw >> 4) * 2 + wp_i;
        int lat_p = (wdw & 15) * 6 + wa_i;
        int rpl  = pl_p  < 6  ? 0 : (pl_p  < 7  ? 1 : 2);
        int rlat = lat_p < 90 ? 0 : (lat_p < 93 ? 1 : 2);
        int base = (rpl * 3 + rlat) * 3;
        sid0[n]  = base;
        sid14[n] = base + ((168 + wo_i) >= 174 ? 1 : 0);
    }
    {
        const float* bt = g_btabT + (size_t)(wdw * NHEAD + head) * BROWS;
        for (int e = tid; e < NTOK * NTOK; e += 288) {
            int i = e / NTOK, j = e - i * NTOK;
            int zi = i / 72, hi = (i / 12) % 6, wi = i % 12;
            int zj = j / 72, hj = (j / 12) % 6, wj = j % 12;
            int bidx = (zi + 2 * zj) * 828 + (hi + 6 * hj) * 23 + (wi - wj + 11);
            sbias[i * PADB + j] = __float2bfloat16(bt[bidx]);
        }
    }

    const int qrow0 = warp * 16;
    const int g = lane >> 2, c4 = lane & 3;
    const int row0 = qrow0 + g, row1 = row0 + 8;
    const float qscale = 0.17677669529663687f;

    for (int li = 0; li < NLON; li++) {
        if (li + 1 < NLON) {
            load_st((li + 1) & 1, li + 1);
            asm volatile("cp.async.commit_group;\n");
            asm volatile("cp.async.wait_group 1;\n");
        } else {
            asm volatile("cp.async.wait_group 0;\n");
        }
        __syncthreads();

        uint32_t sq_b = squ + (li & 1) * STAGEB;
        uint32_t sk_b = sq_b + MATB;
        uint32_t sv_b = sk_b + MATB;
        const int* sregp = (li == 14) ? sid14 : sid0;

        uint32_t aq[2][4];
        #pragma unroll
        for (int kkidx = 0; kkidx < 2; kkidx++) {
            uint32_t addr = sq_b + (uint32_t)((qrow0 + (lane & 15)) * (APAD * 2)
                                              + kkidx * 32 + (lane & 16));
            ldsm4(aq[kkidx], addr);
        }

        float sacc[18][4];
        #pragma unroll
        for (int t = 0; t < 18; t++)
            #pragma unroll
            for (int c = 0; c < 4; c++) sacc[t][c] = 0.f;

        #pragma unroll
        for (int nt = 0; nt < 9; nt++) {
            #pragma unroll
            for (int kkidx = 0; kkidx < 2; kkidx++) {
                uint32_t bk[4];
                uint32_t addr = sk_b +
                    (uint32_t)((nt * 16 + (lane & 7) + ((lane & 16) >> 1)) * (APAD * 2)
                               + kkidx * 32 + (lane & 8) * 2);
                ldsm4(bk, addr);
                mma16816(sacc[2 * nt],     aq[kkidx], &bk[0]);
                mma16816(sacc[2 * nt + 1], aq[kkidx], &bk[2]);
            }
        }

        const int rg0 = sregp[row0], rg1 = sregp[row1];
        #pragma unroll
        for (int t = 0; t < 18; t++) {
            int col = t * 8 + 2 * c4;
            float2 b0 = __bfloat1622float2(*(const __nv_bfloat162*)(sbias + row0 * PADB + col));
            float2 b1 = __bfloat1622float2(*(const __nv_bfloat162*)(sbias + row1 * PADB + col));
            int rc0 = sregp[col], rc1 = sregp[col + 1];
            sacc[t][0] = fmaf(sacc[t][0], qscale, b0.x + (rc0 != rg0 ? -100.f : 0.f));
            sacc[t][1] = fmaf(sacc[t][1], qscale, b0.y + (rc1 != rg0 ? -100.f : 0.f));
            sacc[t][2] = fmaf(sacc[t][2], qscale, b1.x + (rc0 != rg1 ? -100.f : 0.f));
            sacc[t][3] = fmaf(sacc[t][3], qscale, b1.y + (rc1 != rg1 ? -100.f : 0.f));
        }

        float mx0 = -1e30f, mx1 = -1e30f;
        #pragma unroll
        for (int t = 0; t < 18; t++) {
            mx0 = fmaxf(mx0, fmaxf(sacc[t][0], sacc[t][1]));
            mx1 = fmaxf(mx1, fmaxf(sacc[t][2], sacc[t][3]));
        }
        #pragma unroll
        for (int o = 1; o <= 2; o <<= 1) {
            mx0 = fmaxf(mx0, __shfl_xor_sync(0xffffffffu, mx0, o));
            mx1 = fmaxf(mx1, __shfl_xor_sync(0xffffffffu, mx1, o));
        }
        float sum0 = 0.f, sum1 = 0.f;
        #pragma unroll
        for (int t = 0; t < 18; t++) {
            sacc[t][0] = __expf(sacc[t][0] - mx0);
            sacc[t][1] = __expf(sacc[t][1] - mx0);
            sacc[t][2] = __expf(sacc[t][2] - mx1);
            sacc[t][3] = __expf(sacc[t][3] - mx1);
            sum0 += sacc[t][0] + sacc[t][1];
            sum1 += sacc[t][2] + sacc[t][3];
        }
        #pragma unroll
        for (int o = 1; o <= 2; o <<= 1) {
            sum0 += __shfl_xor_sync(0xffffffffu, sum0, o);
            sum1 += __shfl_xor_sync(0xffffffffu, sum1, o);
        }
        float inv0 = 1.f / sum0, inv1 = 1.f / sum1;

        uint32_t ap[9][4];
        #pragma unroll
        for (int kt = 0; kt < 9; kt++) {
            ap[kt][0] = packbf2(sacc[2 * kt][0],     sacc[2 * kt][1]);
            ap[kt][1] = packbf2(sacc[2 * kt][2],     sacc[2 * kt][3]);
            ap[kt][2] = packbf2(sacc[2 * kt + 1][0], sacc[2 * kt + 1][1]);
            ap[kt][3] = packbf2(sacc[2 * kt + 1][2], sacc[2 * kt + 1][3]);
        }

        float oacc[4][4];
        #pragma unroll
        for (int t = 0; t < 4; t++)
            #pragma unroll
            for (int c = 0; c < 4; c++) oacc[t][c] = 0.f;

        #pragma unroll
        for (int kt = 0; kt < 9; kt++) {
            #pragma unroll
            for (int dh = 0; dh < 2; dh++) {
                uint32_t bv[4];
                uint32_t addr = sv_b +
                    (uint32_t)((kt * 16 + (lane & 15)) * (APAD * 2) + dh * 32 + (lane & 16));
                ldsm4t(bv, addr);
                mma16816(oacc[2 * dh],     ap[kt], &bv[0]);
                mma16816(oacc[2 * dh + 1], ap[kt], &bv[2]);
            }
        }

        int bw = li * NWIN + wdw;
        #pragma unroll
        for (int dt = 0; dt < 4; dt++) {
            int col = head * HDIM + dt * 8 + 2 * c4;
            size_t t0 = (size_t)(bw * NTOK + row0) * DIMC + col;
            size_t t1 = (size_t)(bw * NTOK + row1) * DIMC + col;
            *(__nv_bfloat162*)(g_attnout + t0) =
                __nv_bfloat162(__float2bfloat16(oacc[dt][0] * inv0), __float2bfloat16(oacc[dt][1] * inv0));
            *(__nv_bfloat162*)(g_attnout + t1) =
                __nv_bfloat162(__float2bfloat16(oacc[dt][2] * inv1), __float2bfloat16(oacc[dt][3] * inv1));
        }
        __syncthreads();
    }
}

// ---------------- un-window + residual + LN2 (warp per token) ----------------
__global__ __launch_bounds__(256) void unwin_res_ln2_kernel(const float* __restrict__ x,
                                                             const float* __restrict__ w,
                                                             const float* __restrict__ b) {
    int t = blockIdx.x * 8 + (threadIdx.x >> 5);
    int lane = threadIdx.x & 31;
    int pl = t / (91 * 180);
    int rem = t - pl * (91 * 180);
    int lat = rem / 180, lon = rem % 180;
    int pl_p  = (pl + 7) & 7;
    int lat_p = (lat + 95) % 96;
    int lon_p = (lon + 174) % 180;
    int plg = pl_p >> 1, wp_i = pl_p & 1;
    int latg = lat_p / 6, wa_i = lat_p % 6;
    int li = lon_p / 12, wo_i = lon_p % 12;
    int wdw = plg * 16 + latg;
    int n = (wp_i * 6 + wa_i) * 12 + wo_i;
    size_t slot = ((size_t)((li * NWIN + wdw) * NTOK + n)) * DIMC;
    size_t base = (size_t)t * DIMC;
    float v[6]; float s = 0.f, s2 = 0.f;
    #pragma unroll
    for (int k = 0; k < 6; k++) {
        int c = lane + 32 * k;
        float vv = x[base + c] + __bfloat162float(g_projout[slot + c]);
        v[k] = vv; s += vv; s2 += vv * vv;
        g_x1[base + c] = vv;
    }
    #pragma unroll
    for (int o = 16; o > 0; o >>= 1) {
        s  += __shfl_xor_sync(0xffffffffu, s, o);
        s2 += __shfl_xor_sync(0xffffffffu, s2, o);
    }
    float mean = s * (1.f / 192.f);
    float var  = s2 * (1.f / 192.f) - mean * mean;
    float rstd = rsqrtf(var + 1e-5f);
    #pragma unroll
    for (int k = 0; k < 6; k++) {
        int c = lane + 32 * k;
        float h = (v[k] - mean) * rstd * w[c] + b[c];
        g_h2in[base + c] = __float2bfloat16(h);
    }
}

// ---------------- launch ----------------
extern "C" void kernel_launch(void* const* d_in, const int* in_sizes, int n_in,
                              void* d_out, int out_size) {
    const float* x     = (const float*)d_in[0];
    const float* n1w   = (const float*)d_in[1];
    const float* n1b   = (const float*)d_in[2];
    const float* qkvw  = (const float*)d_in[3];
    const float* qkvb  = (const float*)d_in[4];
    const float* btab  = (const float*)d_in[5];
    const float* projw = (const float*)d_in[6];
    const float* projb = (const float*)d_in[7];
    const float* n2w   = (const float*)d_in[8];
    const float* n2b   = (const float*)d_in[9];
    const float* fc1w  = (const float*)d_in[10];
    const float* fc1b  = (const float*)d_in[11];
    const float* fc2w  = (const float*)d_in[12];
    const float* fc2b  = (const float*)d_in[13];
    float* out = (float*)d_out;

    void *pA1, *pqkv, *pattn, *pproj, *px1, *ph2in, *ph2mid;
    void *pwqkv, *pwproj, *pwfc1, *pwfc2;
    cudaGetSymbolAddress(&pA1, g_A1);
    cudaGetSymbolAddress(&pqkv, g_qkv);
    cudaGetSymbolAddress(&pattn, g_attnout);
    cudaGetSymbolAddress(&pproj, g_projout);
    cudaGetSymbolAddress(&px1, g_x1);
    cudaGetSymbolAddress(&ph2in, g_h2in);
    cudaGetSymbolAddress(&ph2mid, g_h2mid);
    cudaGetSymbolAddress(&pwqkv, g_wqkv);
    cudaGetSymbolAddress(&pwproj, g_wproj);
    cudaGetSymbolAddress(&pwfc1, g_wfc1);
    cudaGetSymbolAddress(&pwfc2, g_wfc2);

    cudaFuncSetAttribute(gemm2<1>, cudaFuncAttributeMaxDynamicSharedMemorySize, GEMM_SMEM);
    cudaFuncSetAttribute(gemm2<2>, cudaFuncAttributeMaxDynamicSharedMemorySize, GEMM_SMEM);
    cudaFuncSetAttribute(gemm2<3>, cudaFuncAttributeMaxDynamicSharedMemorySize, GEMM_SMEM);
    cudaFuncSetAttribute(attn_kernel, cudaFuncAttributeMaxDynamicSharedMemorySize, ATTN_SMEM);

    // 1: merged weight conversions
    wconv_kernel<<<1728, 256>>>(qkvw, projw, fc1w, fc2w);

    // 2: bias table transpose
    btab_t_kernel<<<(BROWS * NWIN * NHEAD + 255) / 256, 256>>>(btab);

    // 3: LN1 + window partition
    ln1_window_kernel<<<TOKW / 8, 256>>>(x, n1w, n1b);

    // 4: QKV GEMM -> bf16
    gemm2<1><<<dim3(3, TOKW / BM), 256, GEMM_SMEM>>>(TOKW, 3 * DIMC, DIMC,
        (const __nv_bfloat16*)pA1, (const __nv_bfloat16*)pwqkv, qkvb,
        (__nv_bfloat16*)pqkv, nullptr, nullptr);

    // 5: fused windowed attention
    attn_kernel<<<dim3(NHEAD, NWIN), 288, ATTN_SMEM>>>();

    // 6: proj GEMM -> bf16 (window layout)
    gemm2<1><<<dim3(1, TOKW / BM), 256, GEMM_SMEM>>>(TOKW, DIMC, DIMC,
        (const __nv_bfloat16*)pattn, (const __nv_bfloat16*)pwproj, projb,
        (__nv_bfloat16*)pproj, nullptr, nullptr);

    // 7: un-window + residual + LN2
    unwin_res_ln2_kernel<<<L_TOK / 8, 256>>>(x, n2w, n2b);

    // 8: fc1 (+ exact GELU) -> bf16
    gemm2<2><<<dim3(4, (L_TOK + BM - 1) / BM), 256, GEMM_SMEM>>>(L_TOK, HID, DIMC,
        (const __nv_bfloat16*)ph2in, (const __nv_bfloat16*)pwfc1, fc1b,
        (__nv_bfloat16*)ph2mid, nullptr, nullptr);

    // 9: fc2 + residual -> d_out
    gemm2<3><<<dim3(1, (L_TOK + BM - 1) / BM), 256, GEMM_SMEM>>>(L_TOK, DIMC, HID,
        (const __nv_bfloat16*)ph2mid, (const __nv_bfloat16*)pwfc2, fc2b,
        nullptr, (const float*)px1, out);
}

// round 8
// speedup vs baseline: 3.4130x; 1.1674x over previous
#include <cuda_runtime.h>
#include <cuda_bf16.h>
#include <math.h>
#include <stdint.h>

// ---------------- problem constants ----------------
#define L_TOK   131040          // 8*91*180
#define TOKW    138240          // 960 windows * 144 tokens
#define DIMC    192
#define HID     768
#define NHEAD   6
#define HDIM    32
#define NTOK    144             // tokens per window (2*6*12)
#define NWIN    64              // windows per lon-group (4*16)
#define NLON    15
#define BWN     960             // NLON*NWIN
#define BROWS   3312            // bias table rows: 4*36*23

// GEMM tiling (SW128 swizzled smem, BK=64, 2 CTAs / SM)
#define BM 64
#define BN 192
#define BK 64
#define GSTAGES 3
#define ASTG (BM * 128)                  // 8192 B
#define BSTG (BN * 128)                  // 24576 B
#define STGB (ASTG + BSTG)               // 32768 B
#define GEMM_SMEM (STGB * GSTAGES)       // 98304 B

// attention smem layout
#define APAD 40                          // row stride in halves for q/k/v
#define MATH (NTOK * APAD)               // 5760 halves per matrix
#define MATB (MATH * 2)                  // 11520 bytes
#define STAGEB (3 * MATB)                // 34560 bytes per stage
#define PADB 146                         // bias row stride (halves)
#define BIASB (NTOK * PADB * 2)          // 42048 bytes
#define ATTN_SMEM (2 * STAGEB + BIASB + 2 * NTOK * 4)   // 112320

// ---------------- scratch buffers ----------------
__device__ __nv_bfloat16 g_A1[(size_t)TOKW * DIMC];
__device__ __nv_bfloat16 g_qkv[(size_t)TOKW * 3 * DIMC];
__device__ float         g_btabT[(size_t)NWIN * NHEAD * BROWS];   // [b2][bidx]
__device__ __nv_bfloat16 g_attnout[(size_t)TOKW * DIMC];
__device__ __nv_bfloat16 g_projout[(size_t)TOKW * DIMC];
__device__ float         g_x1[(size_t)L_TOK * DIMC];
__device__ __nv_bfloat16 g_h2in[(size_t)L_TOK * DIMC];
__device__ __nv_bfloat16 g_h2mid[(size_t)L_TOK * HID];
__device__ __nv_bfloat16 g_wqkv[3 * DIMC * DIMC];
__device__ __nv_bfloat16 g_wproj[DIMC * DIMC];
__device__ __nv_bfloat16 g_wfc1[HID * DIMC];
__device__ __nv_bfloat16 g_wfc2[DIMC * HID];

// ---------------- helpers ----------------
__device__ __forceinline__ void cp_async16(uint32_t saddr, const void* gptr, bool pred) {
    int sz = pred ? 16 : 0;
    asm volatile("cp.async.cg.shared.global [%0], [%1], 16, %2;\n"
                 :: "r"(saddr), "l"(gptr), "r"(sz));
}

__device__ __forceinline__ void ldsm4(uint32_t* r, uint32_t addr) {
    asm volatile("ldmatrix.sync.aligned.m8n8.x4.shared.b16 {%0,%1,%2,%3}, [%4];\n"
                 : "=r"(r[0]), "=r"(r[1]), "=r"(r[2]), "=r"(r[3]) : "r"(addr));
}

__device__ __forceinline__ void ldsm4t(uint32_t* r, uint32_t addr) {
    asm volatile("ldmatrix.sync.aligned.m8n8.x4.trans.shared.b16 {%0,%1,%2,%3}, [%4];\n"
                 : "=r"(r[0]), "=r"(r[1]), "=r"(r[2]), "=r"(r[3]) : "r"(addr));
}

__device__ __forceinline__ void mma16816(float* d, const uint32_t* a, const uint32_t* b) {
    asm volatile(
        "mma.sync.aligned.m16n8k16.row.col.f32.bf16.bf16.f32 "
        "{%0,%1,%2,%3}, {%4,%5,%6,%7}, {%8,%9}, {%0,%1,%2,%3};\n"
        : "+f"(d[0]), "+f"(d[1]), "+f"(d[2]), "+f"(d[3])
        : "r"(a[0]), "r"(a[1]), "r"(a[2]), "r"(a[3]), "r"(b[0]), "r"(b[1]));
}

__device__ __forceinline__ uint32_t packbf2(float lo, float hi) {
    __nv_bfloat162 p = __nv_bfloat162(__float2bfloat16(lo), __float2bfloat16(hi));
    return *reinterpret_cast<uint32_t*>(&p);
}

// ---------------- merged weight conversion ----------------
__global__ __launch_bounds__(256) void wconv_kernel(
    const float* __restrict__ s0, const float* __restrict__ s1,
    const float* __restrict__ s2, const float* __restrict__ s3) {
    int i = blockIdx.x * 256 + threadIdx.x;
    if (i < 110592)      g_wqkv[i]  = __float2bfloat16(s0[i]);
    else if (i < 147456) { int j = i - 110592;  g_wproj[j] = __float2bfloat16(s1[j]); }
    else if (i < 294912) { int j = i - 147456;  g_wfc1[j]  = __float2bfloat16(s2[j]); }
    else if (i < 442368) { int j = i - 294912;  g_wfc2[j]  = __float2bfloat16(s3[j]); }
}

// ---------------- bias table transpose: [bidx][b2] -> [b2][bidx] ----------------
__global__ __launch_bounds__(256) void btab_t_kernel(const float* __restrict__ btab) {
    int e = blockIdx.x * 256 + threadIdx.x;
    if (e < BROWS * NWIN * NHEAD) {
        int b2 = e / BROWS, bidx = e - b2 * BROWS;
        g_btabT[e] = btab[(size_t)bidx * (NWIN * NHEAD) + b2];
    }
}

// ---------------- LN1 + pad + roll + window partition (warp per token) ----------------
__global__ __launch_bounds__(256) void ln1_window_kernel(const float* __restrict__ x,
                                                          const float* __restrict__ w,
                                                          const float* __restrict__ b) {
    int t = blockIdx.x * 8 + (threadIdx.x >> 5);
    int lane = threadIdx.x & 31;
    int bw = t / NTOK, n = t - bw * NTOK;
    int li = bw >> 6, wdw = bw & 63;
    int wp_i = n / 72, wa_i = (n / 12) % 6, wo_i = n % 12;
    int pl_p  = (wdw >> 4) * 2 + wp_i;
    int lat_p = (wdw & 15) * 6 + wa_i;
    int lon_p = li * 12 + wo_i;
    int pl_s  = (pl_p + 1) & 7;
    int lat_s = (lat_p + 3) % 96;
    int lon_s = (lon_p + 6) % 180;
    int lat_o = lat_s - 2;
    bool valid = (lat_o >= 0) && (lat_o < 91);
    size_t src = valid ? ((size_t)(pl_s * 91 + lat_o) * 180 + lon_s) * DIMC : 0;
    float v[6]; float s = 0.f, s2 = 0.f;
    #pragma unroll
    for (int k = 0; k < 6; k++) {
        float vv = valid ? x[src + lane + 32 * k] : 0.f;
        v[k] = vv; s += vv; s2 += vv * vv;
    }
    #pragma unroll
    for (int o = 16; o > 0; o >>= 1) {
        s  += __shfl_xor_sync(0xffffffffu, s, o);
        s2 += __shfl_xor_sync(0xffffffffu, s2, o);
    }
    float mean = s * (1.f / 192.f);
    float var  = s2 * (1.f / 192.f) - mean * mean;
    float rstd = rsqrtf(var + 1e-5f);
    #pragma unroll
    for (int k = 0; k < 6; k++) {
        int c = lane + 32 * k;
        float h = valid ? (v[k] - mean) * rstd * w[c] + b[c] : 0.f;
        g_A1[(size_t)t * DIMC + c] = __float2bfloat16(h);
    }
}

// ---------------- bf16 GEMM: BK=64, SW128 swizzle, 2 CTAs/SM, warp tile 32x48 ----------
// MODE 1: bf16 out + bias   MODE 2: gelu(acc+bias) -> bf16   MODE 3: Out = X1 + acc + bias (fp32)
template <int MODE>
__global__ __launch_bounds__(256, 2) void gemm2(
    int M, int N, int K,
    const __nv_bfloat16* __restrict__ A,
    const __nv_bfloat16* __restrict__ Bw,
    const float* __restrict__ bias,
    __nv_bfloat16* __restrict__ Cb,
    const float* __restrict__ X1,
    float* __restrict__ Out) {
    extern __shared__ __align__(16) unsigned char smraw[];
    uint32_t smem_u32 = (uint32_t)__cvta_generic_to_shared(smraw);

    const int tid = threadIdx.x;
    const int lane = tid & 31, warp = tid >> 5;
    const int m0 = blockIdx.y * BM;
    const int n0 = blockIdx.x * BN;
    const int wm = (warp >> 2) * 32;   // 2 warp rows * 32
    const int wn = (warp & 3) * 48;    // 4 warp cols * 48
    const int KT = K >> 6;             // k-chunks of 64

    float acc[2][6][4];
    #pragma unroll
    for (int a = 0; a < 2; a++)
        #pragma unroll
        for (int b2 = 0; b2 < 6; b2++)
            #pragma unroll
            for (int c = 0; c < 4; c++) acc[a][b2][c] = 0.f;

    // swizzled stage load: row has 8 x 16B chunks; physical chunk = c ^ (row & 7)
    auto load_stage = [&](int stage, int kt) {
        const int kb = kt << 6;
        uint32_t abase = smem_u32 + stage * STGB;
        #pragma unroll
        for (int it = 0; it < 2; it++) {   // A: 64 rows * 8 chunks = 512
            int q = tid + it * 256;
            int row = q >> 3, c = q & 7;
            int gr = m0 + row;
            bool p = gr < M;
            const __nv_bfloat16* gp = A + (size_t)(p ? gr : 0) * K + kb + c * 8;
            cp_async16(abase + (uint32_t)(row * 128 + ((c ^ (row & 7)) << 4)), gp, p);
        }
        uint32_t bbase = abase + ASTG;
        #pragma unroll
        for (int it = 0; it < 6; it++) {   // B: 192 rows * 8 chunks = 1536
            int q = tid + it * 256;
            int row = q >> 3, c = q & 7;
            const __nv_bfloat16* gp = Bw + (size_t)(n0 + row) * K + kb + c * 8;
            cp_async16(bbase + (uint32_t)(row * 128 + ((c ^ (row & 7)) << 4)), gp, true);
        }
    };

    #pragma unroll
    for (int s = 0; s < GSTAGES - 1; s++) {
        load_stage(s, s);
        asm volatile("cp.async.commit_group;\n");
    }

    for (int kt = 0; kt < KT; kt++) {
        asm volatile("cp.async.wait_group 1;\n");
        __syncthreads();
        int kn = kt + GSTAGES - 1;
        if (kn < KT) load_stage(kn % GSTAGES, kn);
        asm volatile("cp.async.commit_group;\n");

        uint32_t abase = smem_u32 + (kt % GSTAGES) * STGB;
        uint32_t bbase = abase + ASTG;
        #pragma unroll
        for (int t = 0; t < 4; t++) {      // 4 k16 steps inside the 64-chunk
            uint32_t af[2][4], bfr[3][4];
            #pragma unroll
            for (int mi = 0; mi < 2; mi++) {
                int r = wm + mi * 16 + (lane & 15);
                int c = 2 * t + ((lane & 16) >> 4);
                ldsm4(af[mi], abase + (uint32_t)(r * 128 + ((c ^ (r & 7)) << 4)));
            }
            #pragma unroll
            for (int nb = 0; nb < 3; nb++) {
                int r = wn + nb * 16 + (lane & 7) + ((lane & 16) >> 1);
                int c = 2 * t + ((lane & 8) >> 3);
                ldsm4(bfr[nb], bbase + (uint32_t)(r * 128 + ((c ^ (r & 7)) << 4)));
            }
            #pragma unroll
            for (int mi = 0; mi < 2; mi++)
                #pragma unroll
                for (int ni = 0; ni < 6; ni++)
                    mma16816(acc[mi][ni], af[mi], &bfr[ni >> 1][(ni & 1) * 2]);
        }
    }

    // epilogue
    const int g = lane >> 2, c4 = lane & 3;
    #pragma unroll
    for (int mi = 0; mi < 2; mi++) {
        #pragma unroll
        for (int ni = 0; ni < 6; ni++) {
            int row0 = m0 + wm + mi * 16 + g;
            int col0 = n0 + wn + ni * 8 + 2 * c4;
            float2 bv = *(const float2*)(bias + col0);
            #pragma unroll
            for (int rr = 0; rr < 2; rr++) {
                int row = row0 + rr * 8;
                if (row >= M) continue;
                float v0 = acc[mi][ni][rr * 2 + 0] + bv.x;
                float v1 = acc[mi][ni][rr * 2 + 1] + bv.y;
                size_t off = (size_t)row * N + col0;
                if (MODE == 1) {
                    *(__nv_bfloat162*)(Cb + off) =
                        __nv_bfloat162(__float2bfloat16(v0), __float2bfloat16(v1));
                } else if (MODE == 2) {
                    float g0 = 0.5f * v0 * (1.0f + erff(v0 * 0.70710678118654752f));
                    float g1 = 0.5f * v1 * (1.0f + erff(v1 * 0.70710678118654752f));
                    *(__nv_bfloat162*)(Cb + off) =
                        __nv_bfloat162(__float2bfloat16(g0), __float2bfloat16(g1));
                } else {
                    float2 xv = *(const float2*)(X1 + off);
                    *(float2*)(Out + off) = make_float2(xv.x + v0, xv.y + v1);
                }
            }
        }
    }
}

// ---------------- tensor-core windowed attention, bias reused across 15 lon-groups ----------
__global__ __launch_bounds__(288, 1) void attn_kernel() {
    const int head = blockIdx.x;
    const int wdw = blockIdx.y;
    const int tid = threadIdx.x;
    const int lane = tid & 31;
    const int warp = tid >> 5;

    extern __shared__ __align__(16) unsigned char smraw[];
    __nv_bfloat16* sbias = (__nv_bfloat16*)(smraw + 2 * STAGEB);
    int* sid0  = (int*)(smraw + 2 * STAGEB + BIASB);
    int* sid14 = sid0 + NTOK;
    uint32_t squ = (uint32_t)__cvta_generic_to_shared(smraw);

    auto load_st = [&](int st, int li) {
        int bw = li * NWIN + wdw;
        const __nv_bfloat16* gb = g_qkv + (size_t)bw * NTOK * (3 * DIMC) + head * HDIM;
        uint32_t sb = squ + st * STAGEB;
        #pragma unroll
        for (int s = 0; s < 6; s++) {
            int c = tid + s * 288;
            int mat = c / 576, rem = c - mat * 576, j = rem >> 2, q16 = rem & 3;
            const void* gp = gb + (size_t)j * (3 * DIMC) + mat * DIMC + q16 * 8;
            cp_async16(sb + (uint32_t)(mat * MATB + j * (APAD * 2) + q16 * 16), gp, true);
        }
    };

    load_st(0, 0);
    asm volatile("cp.async.commit_group;\n");

    if (tid < NTOK) {
        int n = tid;
        int wp_i = n / 72, wa_i = (n / 12) % 6, wo_i = n % 12;
        int pl_p  = (wdw >> 4) * 2 + wp_i;
        int lat_p = (wdw & 15) * 6 + wa_i;
        int rpl  = pl_p  < 6  ? 0 : (pl_p  < 7  ? 1 : 2);
        int rlat = lat_p < 90 ? 0 : (lat_p < 93 ? 1 : 2);
        int base = (rpl * 3 + rlat) * 3;
        sid0[n]  = base;
        sid14[n] = base + ((168 + wo_i) >= 174 ? 1 : 0);
    }
    {
        const float* bt = g_btabT + (size_t)(wdw * NHEAD + head) * BROWS;
        for (int e = tid; e < NTOK * NTOK; e += 288) {
            int i = e / NTOK, j = e - i * NTOK;
            int zi = i / 72, hi = (i / 12) % 6, wi = i % 12;
            int zj = j / 72, hj = (j / 12) % 6, wj = j % 12;
            int bidx = (zi + 2 * zj) * 828 + (hi + 6 * hj) * 23 + (wi - wj + 11);
            sbias[i * PADB + j] = __float2bfloat16(bt[bidx]);
        }
    }

    const int qrow0 = warp * 16;
    const int g = lane >> 2, c4 = lane & 3;
    const int row0 = qrow0 + g, row1 = row0 + 8;
    const float qscale = 0.17677669529663687f;

    for (int li = 0; li < NLON; li++) {
        if (li + 1 < NLON) {
            load_st((li + 1) & 1, li + 1);
            asm volatile("cp.async.commit_group;\n");
            asm volatile("cp.async.wait_group 1;\n");
        } else {
            asm volatile("cp.async.wait_group 0;\n");
        }
        __syncthreads();

        uint32_t sq_b = squ + (li & 1) * STAGEB;
        uint32_t sk_b = sq_b + MATB;
        uint32_t sv_b = sk_b + MATB;
        const int* sregp = (li == 14) ? sid14 : sid0;

        uint32_t aq[2][4];
        #pragma unroll
        for (int kkidx = 0; kkidx < 2; kkidx++) {
            uint32_t addr = sq_b + (uint32_t)((qrow0 + (lane & 15)) * (APAD * 2)
                                              + kkidx * 32 + (lane & 16));
            ldsm4(aq[kkidx], addr);
        }

        float sacc[18][4];
        #pragma unroll
        for (int t = 0; t < 18; t++)
            #pragma unroll
            for (int c = 0; c < 4; c++) sacc[t][c] = 0.f;

        #pragma unroll
        for (int nt = 0; nt < 9; nt++) {
            #pragma unroll
            for (int kkidx = 0; kkidx < 2; kkidx++) {
                uint32_t bk[4];
                uint32_t addr = sk_b +
                    (uint32_t)((nt * 16 + (lane & 7) + ((lane & 16) >> 1)) * (APAD * 2)
                               + kkidx * 32 + (lane & 8) * 2);
                ldsm4(bk, addr);
                mma16816(sacc[2 * nt],     aq[kkidx], &bk[0]);
                mma16816(sacc[2 * nt + 1], aq[kkidx], &bk[2]);
            }
        }

        const int rg0 = sregp[row0], rg1 = sregp[row1];
        #pragma unroll
        for (int t = 0; t < 18; t++) {
            int col = t * 8 + 2 * c4;
            float2 b0 = __bfloat1622float2(*(const __nv_bfloat162*)(sbias + row0 * PADB + col));
            float2 b1 = __bfloat1622float2(*(const __nv_bfloat162*)(sbias + row1 * PADB + col));
            int rc0 = sregp[col], rc1 = sregp[col + 1];
            sacc[t][0] = fmaf(sacc[t][0], qscale, b0.x + (rc0 != rg0 ? -100.f : 0.f));
            sacc[t][1] = fmaf(sacc[t][1], qscale, b0.y + (rc1 != rg0 ? -100.f : 0.f));
            sacc[t][2] = fmaf(sacc[t][2], qscale, b1.x + (rc0 != rg1 ? -100.f : 0.f));
            sacc[t][3] = fmaf(sacc[t][3], qscale, b1.y + (rc1 != rg1 ? -100.f : 0.f));
        }

        float mx0 = -1e30f, mx1 = -1e30f;
        #pragma unroll
        for (int t = 0; t < 18; t++) {
            mx0 = fmaxf(mx0, fmaxf(sacc[t][0], sacc[t][1]));
            mx1 = fmaxf(mx1, fmaxf(sacc[t][2], sacc[t][3]));
        }
        #pragma unroll
        for (int o = 1; o <= 2; o <<= 1) {
            mx0 = fmaxf(mx0, __shfl_xor_sync(0xffffffffu, mx0, o));
            mx1 = fmaxf(mx1, __shfl_xor_sync(0xffffffffu, mx1, o));
        }
        float sum0 = 0.f, sum1 = 0.f;
        #pragma unroll
        for (int t = 0; t < 18; t++) {
            sacc[t][0] = __expf(sacc[t][0] - mx0);
            sacc[t][1] = __expf(sacc[t][1] - mx0);
            sacc[t][2] = __expf(sacc[t][2] - mx1);
            sacc[t][3] = __expf(sacc[t][3] - mx1);
            sum0 += sacc[t][0] + sacc[t][1];
            sum1 += sacc[t][2] + sacc[t][3];
        }
        #pragma unroll
        for (int o = 1; o <= 2; o <<= 1) {
            sum0 += __shfl_xor_sync(0xffffffffu, sum0, o);
            sum1 += __shfl_xor_sync(0xffffffffu, sum1, o);
        }
        float inv0 = 1.f / sum0, inv1 = 1.f / sum1;

        uint32_t ap[9][4];
        #pragma unroll
        for (int kt = 0; kt < 9; kt++) {
            ap[kt][0] = packbf2(sacc[2 * kt][0],     sacc[2 * kt][1]);
            ap[kt][1] = packbf2(sacc[2 * kt][2],     sacc[2 * kt][3]);
            ap[kt][2] = packbf2(sacc[2 * kt + 1][0], sacc[2 * kt + 1][1]);
            ap[kt][3] = packbf2(sacc[2 * kt + 1][2], sacc[2 * kt + 1][3]);
        }

        float oacc[4][4];
        #pragma unroll
        for (int t = 0; t < 4; t++)
            #pragma unroll
            for (int c = 0; c < 4; c++) oacc[t][c] = 0.f;

        #pragma unroll
        for (int kt = 0; kt < 9; kt++) {
            #pragma unroll
            for (int dh = 0; dh < 2; dh++) {
                uint32_t bv[4];
                uint32_t addr = sv_b +
                    (uint32_t)((kt * 16 + (lane & 15)) * (APAD * 2) + dh * 32 + (lane & 16));
                ldsm4t(bv, addr);
                mma16816(oacc[2 * dh],     ap[kt], &bv[0]);
                mma16816(oacc[2 * dh + 1], ap[kt], &bv[2]);
            }
        }

        int bw = li * NWIN + wdw;
        #pragma unroll
        for (int dt = 0; dt < 4; dt++) {
            int col = head * HDIM + dt * 8 + 2 * c4;
            size_t t0 = (size_t)(bw * NTOK + row0) * DIMC + col;
            size_t t1 = (size_t)(bw * NTOK + row1) * DIMC + col;
            *(__nv_bfloat162*)(g_attnout + t0) =
                __nv_bfloat162(__float2bfloat16(oacc[dt][0] * inv0), __float2bfloat16(oacc[dt][1] * inv0));
            *(__nv_bfloat162*)(g_attnout + t1) =
                __nv_bfloat162(__float2bfloat16(oacc[dt][2] * inv1), __float2bfloat16(oacc[dt][3] * inv1));
        }
        __syncthreads();
    }
}

// ---------------- un-window + residual + LN2 (warp per token) ----------------
__global__ __launch_bounds__(256) void unwin_res_ln2_kernel(const float* __restrict__ x,
                                                             const float* __restrict__ w,
                                                             const float* __restrict__ b) {
    int t = blockIdx.x * 8 + (threadIdx.x >> 5);
    int lane = threadIdx.x & 31;
    int pl = t / (91 * 180);
    int rem = t - pl * (91 * 180);
    int lat = rem / 180, lon = rem % 180;
    int pl_p  = (pl + 7) & 7;
    int lat_p = (lat + 95) % 96;
    int lon_p = (lon + 174) % 180;
    int plg = pl_p >> 1, wp_i = pl_p & 1;
    int latg = lat_p / 6, wa_i = lat_p % 6;
    int li = lon_p / 12, wo_i = lon_p % 12;
    int wdw = plg * 16 + latg;
    int n = (wp_i * 6 + wa_i) * 12 + wo_i;
    size_t slot = ((size_t)((li * NWIN + wdw) * NTOK + n)) * DIMC;
    size_t base = (size_t)t * DIMC;
    float v[6]; float s = 0.f, s2 = 0.f;
    #pragma unroll
    for (int k = 0; k < 6; k++) {
        int c = lane + 32 * k;
        float vv = x[base + c] + __bfloat162float(g_projout[slot + c]);
        v[k] = vv; s += vv; s2 += vv * vv;
        g_x1[base + c] = vv;
    }
    #pragma unroll
    for (int o = 16; o > 0; o >>= 1) {
        s  += __shfl_xor_sync(0xffffffffu, s, o);
        s2 += __shfl_xor_sync(0xffffffffu, s2, o);
    }
    float mean = s * (1.f / 192.f);
    float var  = s2 * (1.f / 192.f) - mean * mean;
    float rstd = rsqrtf(var + 1e-5f);
    #pragma unroll
    for (int k = 0; k < 6; k++) {
        int c = lane + 32 * k;
        float h = (v[k] - mean) * rstd * w[c] + b[c];
        g_h2in[base + c] = __float2bfloat16(h);
    }
}

// ---------------- launch ----------------
extern "C" void kernel_launch(void* const* d_in, const int* in_sizes, int n_in,
                              void* d_out, int out_size) {
    const float* x     = (const float*)d_in[0];
    const float* n1w   = (const float*)d_in[1];
    const float* n1b   = (const float*)d_in[2];
    const float* qkvw  = (const float*)d_in[3];
    const float* qkvb  = (const float*)d_in[4];
    const float* btab  = (const float*)d_in[5];
    const float* projw = (const float*)d_in[6];
    const float* projb = (const float*)d_in[7];
    const float* n2w   = (const float*)d_in[8];
    const float* n2b   = (const float*)d_in[9];
    const float* fc1w  = (const float*)d_in[10];
    const float* fc1b  = (const float*)d_in[11];
    const float* fc2w  = (const float*)d_in[12];
    const float* fc2b  = (const float*)d_in[13];
    float* out = (float*)d_out;

    void *pA1, *pqkv, *pattn, *pproj, *px1, *ph2in, *ph2mid;
    void *pwqkv, *pwproj, *pwfc1, *pwfc2;
    cudaGetSymbolAddress(&pA1, g_A1);
    cudaGetSymbolAddress(&pqkv, g_qkv);
    cudaGetSymbolAddress(&pattn, g_attnout);
    cudaGetSymbolAddress(&pproj, g_projout);
    cudaGetSymbolAddress(&px1, g_x1);
    cudaGetSymbolAddress(&ph2in, g_h2in);
    cudaGetSymbolAddress(&ph2mid, g_h2mid);
    cudaGetSymbolAddress(&pwqkv, g_wqkv);
    cudaGetSymbolAddress(&pwproj, g_wproj);
    cudaGetSymbolAddress(&pwfc1, g_wfc1);
    cudaGetSymbolAddress(&pwfc2, g_wfc2);

    cudaFuncSetAttribute(gemm2<1>, cudaFuncAttributeMaxDynamicSharedMemorySize, GEMM_SMEM);
    cudaFuncSetAttribute(gemm2<2>, cudaFuncAttributeMaxDynamicSharedMemorySize, GEMM_SMEM);
    cudaFuncSetAttribute(gemm2<3>, cudaFuncAttributeMaxDynamicSharedMemorySize, GEMM_SMEM);
    cudaFuncSetAttribute(attn_kernel, cudaFuncAttributeMaxDynamicSharedMemorySize, ATTN_SMEM);

    // 1: merged weight conversions
    wconv_kernel<<<1728, 256>>>(qkvw, projw, fc1w, fc2w);

    // 2: bias table transpose
    btab_t_kernel<<<(BROWS * NWIN * NHEAD + 255) / 256, 256>>>(btab);

    // 3: LN1 + window partition
    ln1_window_kernel<<<TOKW / 8, 256>>>(x, n1w, n1b);

    // 4: QKV GEMM -> bf16
    gemm2<1><<<dim3(3, TOKW / BM), 256, GEMM_SMEM>>>(TOKW, 3 * DIMC, DIMC,
        (const __nv_bfloat16*)pA1, (const __nv_bfloat16*)pwqkv, qkvb,
        (__nv_bfloat16*)pqkv, nullptr, nullptr);

    // 5: fused windowed attention
    attn_kernel<<<dim3(NHEAD, NWIN), 288, ATTN_SMEM>>>();

    // 6: proj GEMM -> bf16 (window layout)
    gemm2<1><<<dim3(1, TOKW / BM), 256, GEMM_SMEM>>>(TOKW, DIMC, DIMC,
        (const __nv_bfloat16*)pattn, (const __nv_bfloat16*)pwproj, projb,
        (__nv_bfloat16*)pproj, nullptr, nullptr);

    // 7: un-window + residual + LN2
    unwin_res_ln2_kernel<<<L_TOK / 8, 256>>>(x, n2w, n2b);

    // 8: fc1 (+ exact GELU) -> bf16
    gemm2<2><<<dim3(4, (L_TOK + BM - 1) / BM), 256, GEMM_SMEM>>>(L_TOK, HID, DIMC,
        (const __nv_bfloat16*)ph2in, (const __nv_bfloat16*)pwfc1, fc1b,
        (__nv_bfloat16*)ph2mid, nullptr, nullptr);

    // 9: fc2 + residual -> d_out
    gemm2<3><<<dim3(1, (L_TOK + BM - 1) / BM), 256, GEMM_SMEM>>>(L_TOK, DIMC, HID,
        (const __nv_bfloat16*)ph2mid, (const __nv_bfloat16*)pwfc2, fc2b,
        nullptr, (const float*)px1, out);
}